// round 13
// baseline (speedup 1.0000x reference)
#include <cuda_runtime.h>
#include <cuda_bf16.h>
#include <cuda_fp16.h>
#include <cstdint>
#include <math.h>

// Problem constants
#define BATCH   2
#define SEQ     2048
#define CDIM    1024
#define HEADS   16
#define HDIM    64
#define GAMMA_F 8.0f
#define SCALE_F 0.125f
#define MROWS   (BATCH*SEQ)          // 4096
#define KDIM    1024

// ---------------- scratch (device globals; no allocation allowed) ----------
__device__ float g_qraw[MROWS * 2 * CDIM];
__device__ float g_kraw[MROWS * 2 * CDIM];
__device__ float g_v   [MROWS * CDIM];

// fp16 GEMM operands (pre-swizzled tile-blocked layouts) -- ALL single fp16
__device__ __half g_x  [MROWS * CDIM];
__device__ __half g_a  [MROWS * CDIM];
__device__ __half g_wq [2 * CDIM * CDIM];
__device__ __half g_wk [2 * CDIM * CDIM];
__device__ __half g_wv [CDIM * CDIM];
__device__ __half g_wo [CDIM * CDIM];

// attention operands: ALL single fp16
__device__ __half g_qr [MROWS * CDIM];
__device__ __half g_qi [MROWS * CDIM];
__device__ __half g_kr [MROWS * CDIM];
__device__ __half g_ki [MROWS * CDIM];
__device__ __half g_vv [MROWS * CDIM];
__device__ float2 g_gate[HEADS * SEQ];

// ---------------- helpers ---------------------------------------------------
__device__ __forceinline__ uint32_t smem_u32(const void* p) {
    uint32_t a;
    asm("{ .reg .u64 t; cvta.to.shared.u64 t, %1; cvt.u32.u64 %0, t; }"
        : "=r"(a) : "l"(p));
    return a;
}
#define SWZ128(o) ((o) ^ (((o) >> 3) & 0x70))

__device__ __forceinline__ size_t gemmA_off(int row, int col) {
    return ((size_t)((row >> 7) * 16 + (col >> 6)) << 14) +
           SWZ128((uint32_t)((row & 127) * 128 + (col & 63) * 2));
}
__device__ __forceinline__ size_t att_off(int b, int h, int t, int d) {
    return ((size_t)((b * HEADS + h) * 32 + (t >> 6)) << 13) +
           SWZ128((uint32_t)((t & 63) * 128 + d * 2));
}

#define MBARRIER_INIT(mbar, count) \
    asm volatile("mbarrier.init.shared.b64 [%0], %1;" :: "r"((uint32_t)(mbar)), "r"((uint32_t)(count)) : "memory")
#define MBAR_EXPECT(mbar, bytes) \
    asm volatile("mbarrier.arrive.expect_tx.shared.b64 _, [%0], %1;" :: "r"((uint32_t)(mbar)), "r"((uint32_t)(bytes)) : "memory")

#define MBARRIER_WAIT_PARITY(mbar, parity) do { \
    uint32_t _m = (uint32_t)(mbar); uint32_t _p = (uint32_t)(parity); uint32_t _d; \
    asm volatile("{\n\t.reg .pred p;\n\t" \
        "mbarrier.try_wait.parity.acquire.cta.shared::cta.b64 p, [%1], %2;\n\t" \
        "selp.b32 %0, 1, 0, p;\n\t}" : "=r"(_d) : "r"(_m), "r"(_p) : "memory"); \
    if (!_d) { \
        asm volatile("{\n\t.reg .pred P1;\n\t" \
            "WL_%=:\n\t" \
            "mbarrier.try_wait.parity.acquire.cta.shared::cta.b64 P1, [%0], %1, 0x989680;\n\t" \
            "@P1 bra.uni WD_%=;\n\tbra.uni WL_%=;\n\tWD_%=:\n\t}" \
            :: "r"(_m), "r"(_p) : "memory"); \
    } } while (0)

__device__ __forceinline__ void bulk_g2s(uint32_t dst, const void* src,
                                         uint32_t bytes, uint32_t mbar) {
    asm volatile(
        "cp.async.bulk.shared::cluster.global.mbarrier::complete_tx::bytes [%0], [%1], %2, [%3];"
        :: "r"(dst), "l"(src), "r"(bytes), "r"(mbar) : "memory");
}

__device__ __forceinline__ void ldsm_x4(uint32_t& r0, uint32_t& r1,
                                        uint32_t& r2, uint32_t& r3, uint32_t addr) {
    asm volatile("ldmatrix.sync.aligned.m8n8.x4.shared.b16 {%0,%1,%2,%3}, [%4];"
                 : "=r"(r0), "=r"(r1), "=r"(r2), "=r"(r3) : "r"(addr));
}
__device__ __forceinline__ void ldsm_x4_t(uint32_t& r0, uint32_t& r1,
                                          uint32_t& r2, uint32_t& r3, uint32_t addr) {
    asm volatile("ldmatrix.sync.aligned.m8n8.x4.trans.shared.b16 {%0,%1,%2,%3}, [%4];"
                 : "=r"(r0), "=r"(r1), "=r"(r2), "=r"(r3) : "r"(addr));
}

__device__ __forceinline__ void mma_fp16(float* c, const uint32_t* a,
                                         uint32_t b0, uint32_t b1) {
    asm volatile(
        "mma.sync.aligned.m16n8k16.row.col.f32.f16.f16.f32 "
        "{%0,%1,%2,%3}, {%4,%5,%6,%7}, {%8,%9}, {%0,%1,%2,%3};"
        : "+f"(c[0]), "+f"(c[1]), "+f"(c[2]), "+f"(c[3])
        : "r"(a[0]), "r"(a[1]), "r"(a[2]), "r"(a[3]), "r"(b0), "r"(b1));
}

__device__ __forceinline__ uint32_t pack_half(float a, float b) {
    __half2 t = __floats2half2_rn(a, b);
    return *reinterpret_cast<uint32_t*>(&t);
}

// ---------------- single-fp16 GEMM: C = A[M,K] * B[N,K]^T -------------------
// Block 128x256, 8 warps 64x64, K-chunk 64, 2-stage bulk pipeline, 1-MMA pass.
// Stage 48KB -> 2 CTAs/SM.
#define BK       64
#define NCH      (KDIM / BK)
#define A_TB     16384
#define STG_B    (3 * A_TB)              // A, B0, B1 = 49152
#define GSTAGES  2
#define GEMM_SMEM (1024 + GSTAGES * STG_B)  // 99328

__device__ __forceinline__ void gemm_body(
    const char* cA, const char* cB, int mb, int nb, float acc[4][8][4]) {
    extern __shared__ char smem[];
    const uint32_t sb = smem_u32(smem);
    const int tid = threadIdx.x, wid = tid >> 5, lane = tid & 31;
    const int wm = (wid & 1) * 64;
    const int wn = (wid >> 1) * 64;

    const size_t mbB = ((size_t)mb * 16) << 14;
    const size_t nbB0 = ((size_t)(nb * 2) * 16) << 14;
    const size_t nbB1 = ((size_t)(nb * 2 + 1) * 16) << 14;

    if (tid == 0) { MBARRIER_INIT(sb, 1); MBARRIER_INIT(sb + 8, 1); }
    __syncthreads();

    auto issue = [&](int chunk, int buf) {
        const uint32_t st = sb + 1024 + buf * STG_B;
        const uint32_t bar = sb + buf * 8;
        const size_t kB = ((size_t)chunk) << 14;
        MBAR_EXPECT(bar, STG_B);
        bulk_g2s(st,            cA + mbB + kB,   A_TB, bar);
        bulk_g2s(st + A_TB,     cB + nbB0 + kB,  A_TB, bar);
        bulk_g2s(st + 2 * A_TB, cB + nbB1 + kB,  A_TB, bar);
    };

    if (tid == 0) { issue(0, 0); issue(1, 1); }

#pragma unroll
    for (int i = 0; i < 4; i++)
#pragma unroll
        for (int j = 0; j < 8; j++)
#pragma unroll
            for (int e = 0; e < 4; e++) acc[i][j][e] = 0.f;

    const int a_row = (lane & 15);
    const uint32_t a_cb = (uint32_t)((lane >> 4) * 16);
    const int b_row = ((lane >> 4) & 1) * 8 + (lane & 7);
    const uint32_t b_cb = (uint32_t)(((lane >> 3) & 1) * 16);

    for (int i = 0; i < NCH; i++) {
        const int stg = i & 1;
        MBARRIER_WAIT_PARITY(sb + stg * 8, (i >> 1) & 1);

        const uint32_t st = sb + 1024 + stg * STG_B;
        const uint32_t aA = st;
        const uint32_t bB = st + A_TB;     // 256 rows contiguous

#pragma unroll
        for (int ks = 0; ks < 4; ks++) {
            const uint32_t kb = (uint32_t)(ks * 32);
            uint32_t af[4][4];
#pragma unroll
            for (int mi = 0; mi < 4; mi++) {
                uint32_t off = SWZ128((uint32_t)((wm + mi * 16 + a_row) * 128) + kb + a_cb);
                ldsm_x4(af[mi][0], af[mi][1], af[mi][2], af[mi][3], aA + off);
            }
#pragma unroll
            for (int hb = 0; hb < 2; hb++) {
                uint32_t bf[2][4];
#pragma unroll
                for (int g2 = 0; g2 < 2; g2++) {
                    const int ng = hb * 2 + g2;
                    uint32_t off = SWZ128((uint32_t)((wn + ng * 16 + b_row) * 128) + kb + b_cb);
                    ldsm_x4(bf[g2][0], bf[g2][1], bf[g2][2], bf[g2][3], bB + off);
                }
#pragma unroll
                for (int g2 = 0; g2 < 2; g2++)
#pragma unroll
                    for (int mi = 0; mi < 4; mi++) {
                        const int nj = 2 * (hb * 2 + g2);
                        mma_fp16(acc[mi][nj],     af[mi], bf[g2][0], bf[g2][1]);
                        mma_fp16(acc[mi][nj + 1], af[mi], bf[g2][2], bf[g2][3]);
                    }
            }
        }
        __syncthreads();
        if (i + GSTAGES < NCH && tid == 0) issue(i + GSTAGES, stg);
    }
}

__device__ __forceinline__ void gemm_store(float acc[4][8][4], float* Cm, int N,
                                           int m0, int n0) {
    const int tid = threadIdx.x, wid = tid >> 5, lane = tid & 31;
    const int wm = (wid & 1) * 64, wn = (wid >> 1) * 64;
    const int cr = lane >> 2;
    const int cc = (lane & 3) * 2;
#pragma unroll
    for (int mi = 0; mi < 4; mi++) {
#pragma unroll
        for (int nj = 0; nj < 8; nj++) {
            const int r = m0 + wm + mi * 16 + cr;
            const int c = n0 + wn + nj * 8 + cc;
            *(float2*)&Cm[(size_t)r * N + c] = make_float2(acc[mi][nj][0], acc[mi][nj][1]);
            *(float2*)&Cm[(size_t)(r + 8) * N + c] = make_float2(acc[mi][nj][2], acc[mi][nj][3]);
        }
    }
}

// Combined Q/K/V projection GEMM: grid.x = 20 (8 Q | 8 K | 4 V), grid.y = 32
__global__ __launch_bounds__(256, 2)
void gemm_qkv(const __half* __restrict__ x,
              const __half* __restrict__ wq, const __half* __restrict__ wk,
              const __half* __restrict__ wv,
              float* __restrict__ qraw, float* __restrict__ kraw, float* __restrict__ vout) {
    const int nx = blockIdx.x;
    const __half* B;
    float* Cm;
    int N, nb;
    if (nx < 8)       { B = wq; Cm = qraw; N = 2 * CDIM; nb = nx; }
    else if (nx < 16) { B = wk; Cm = kraw; N = 2 * CDIM; nb = nx - 8; }
    else              { B = wv; Cm = vout; N = CDIM;     nb = nx - 16; }

    float acc[4][8][4];
    gemm_body((const char*)x, (const char*)B, blockIdx.y, nb, acc);
    gemm_store(acc, Cm, N, blockIdx.y * 128, nb * 256);
}

// Output projection GEMM
__global__ __launch_bounds__(256, 2)
void gemm_out(const __half* __restrict__ A, const __half* __restrict__ B,
              float* __restrict__ Cm, int N) {
    float acc[4][8][4];
    gemm_body((const char*)A, (const char*)B, blockIdx.y, blockIdx.x, acc);
    gemm_store(acc, Cm, N, blockIdx.y * 128, blockIdx.x * 256);
}

// ---------------- fp32 -> single fp16, GEMM-A tiled layout ------------------
__global__ __launch_bounds__(256)
void convert_gemm(const float* __restrict__ src, __half* __restrict__ dst) {
    int i2 = blockIdx.x * 256 + threadIdx.x;
    int row = i2 >> 9, col = (i2 & 511) * 2;
    float2 v = *(const float2*)&src[(size_t)row * CDIM + col];
    size_t off = gemmA_off(row, col);
    *(uint32_t*)((char*)dst + off) = pack_half(v.x, v.y);
}

// fp32 -> single fp16 in ATTENTION tiled layout (for V)
__global__ __launch_bounds__(256)
void convert_att_single(const float* __restrict__ src, __half* __restrict__ dst) {
    int i2 = blockIdx.x * 256 + threadIdx.x;
    int bt = i2 >> 9, col = (i2 & 511) * 2;
    int b = bt >> 11, t = bt & (SEQ - 1);
    int h = col >> 6, d = col & 63;
    float2 v = *(const float2*)&src[(size_t)bt * CDIM + col];
    size_t off = att_off(b, h, t, d);
    *(uint32_t*)((char*)dst + off) = pack_half(v.x, v.y);
}

// ---------------- weight transpose -> single fp16, GEMM-A tiled layout ------
__global__ __launch_bounds__(256)
void transpose_half(const float* __restrict__ W, __half* __restrict__ Hh,
                    int K, int N) {
    __shared__ float t[32][33];
    const int tx = threadIdx.x, ty = threadIdx.y;
    const int n0 = blockIdx.x * 32, k0 = blockIdx.y * 32;
#pragma unroll
    for (int i = 0; i < 32; i += 8)
        t[ty + i][tx] = W[(size_t)(k0 + ty + i) * N + n0 + tx];
    __syncthreads();
#pragma unroll
    for (int i = 0; i < 32; i += 8) {
        float v = t[tx][ty + i];
        size_t off = gemmA_off(n0 + ty + i, k0 + tx);
        *(__half*)((char*)Hh + off) = __float2half(v);
    }
}

// ---------------- amp/phase transform -> single fp16 ------------------------
__device__ __forceinline__ float softplus_f(float a) {
    return (a > 20.f) ? a : log1pf(expf(a));
}

__global__ __launch_bounds__(256)
void transform_qk_fp16() {
    int i2 = blockIdx.x * 256 + threadIdx.x;
    int c2 = i2 * 2;
    int bt = c2 >> 10;
    int c  = c2 & 1023;
    int b = bt >> 11, t = bt & (SEQ - 1);
    int h = c >> 6, d = c & 63;
    size_t rbase = (size_t)bt * (2 * CDIM);
    size_t off = att_off(b, h, t, d);

    float qa0 = g_qraw[rbase + c],        qa1 = g_qraw[rbase + c + 1];
    float qp0 = g_qraw[rbase + CDIM + c], qp1 = g_qraw[rbase + CDIM + c + 1];
    float ka0 = g_kraw[rbase + c],        ka1 = g_kraw[rbase + c + 1];
    float kp0 = g_kraw[rbase + CDIM + c], kp1 = g_kraw[rbase + CDIM + c + 1];

    float qs0 = softplus_f(qa0), qs1 = softplus_f(qa1);
    float ks0 = softplus_f(ka0), ks1 = softplus_f(ka1);
    float s0, c0, s1, c1, s2, c2f, s3, c3;
    sincosf(qp0, &s0, &c0); sincosf(qp1, &s1, &c1);
    sincosf(kp0, &s2, &c2f); sincosf(kp1, &s3, &c3);

    *(uint32_t*)((char*)g_qr + off) = pack_half(qs0 * c0, qs1 * c1);
    *(uint32_t*)((char*)g_qi + off) = pack_half(qs0 * s0, qs1 * s1);
    *(uint32_t*)((char*)g_kr + off) = pack_half(ks0 * c2f, ks1 * c3);
    *(uint32_t*)((char*)g_ki + off) = pack_half(ks0 * s2, ks1 * s3);
}

__global__ void gate_init(const float* __restrict__ theta) {
    int i = blockIdx.x * 256 + threadIdx.x;
    int h = i >> 11, s = i & (SEQ - 1);
    float th = theta[h] * (1.0f / GAMMA_F);
    float sn, cs;
    sincosf(th * (float)s, &sn, &cs);
    g_gate[i] = make_float2(cs, sn);
}

// ---------------- fully fp16 flash attention with moiré gate ----------------
#define AQT 128
#define AST 64
#define AQ_TILE 16384
#define AKV_TILE 8192
#define AKV_BUF (3 * AKV_TILE)              // 24576
#define AKV_STAGES 4
#define ATT_SMEM (1024 + 2 * AQ_TILE + AKV_STAGES * AKV_BUF)  // 132096

__global__ __launch_bounds__(256)
void attn_mma() {
    extern __shared__ char smem[];
    const uint32_t sb = smem_u32(smem);
    const uint32_t sQ  = sb + 1024;
    const uint32_t sKV = sQ + 2 * AQ_TILE;

    const int tid = threadIdx.x, w = tid >> 5, lane = tid & 31;
    const int q0 = (int)(gridDim.x - 1 - blockIdx.x) * AQT;
    const int h = blockIdx.y, b = blockIdx.z;
    const int nS = q0 / AST + 2;

    const size_t bhB = ((size_t)((b * HEADS + h) * 32)) << 13;

    if (tid == 0) {
        MBARRIER_INIT(sb, 1);
#pragma unroll
        for (int s = 0; s < AKV_STAGES; s++) MBARRIER_INIT(sb + 8 + s * 8, 1);
    }
    __syncthreads();

    auto issue_kv = [&](int chunk, int buf) {
        const uint32_t st = sKV + buf * AKV_BUF;
        const uint32_t bar = sb + 8 + buf * 8;
        const size_t src = bhB + (((size_t)chunk) << 13);
        MBAR_EXPECT(bar, AKV_BUF);
        bulk_g2s(st,                (const char*)g_kr + src, AKV_TILE, bar);
        bulk_g2s(st + AKV_TILE,     (const char*)g_ki + src, AKV_TILE, bar);
        bulk_g2s(st + 2 * AKV_TILE, (const char*)g_vv + src, AKV_TILE, bar);
    };

    if (tid == 0) {
        const size_t qsrc = bhB + (((size_t)(q0 >> 6)) << 13);
        MBAR_EXPECT(sb, 2 * AQ_TILE);
        bulk_g2s(sQ,           (const char*)g_qr + qsrc, AQ_TILE, sb);
        bulk_g2s(sQ + AQ_TILE, (const char*)g_qi + qsrc, AQ_TILE, sb);
#pragma unroll
        for (int c = 0; c < AKV_STAGES; c++)
            if (c < nS) issue_kv(c, c);
    }

    const int a_row = lane & 15;
    const uint32_t a_cb = (uint32_t)((lane >> 4) * 16);
    const int b_row = ((lane >> 4) & 1) * 8 + (lane & 7);
    const uint32_t b_cb = (uint32_t)(((lane >> 3) & 1) * 16);

    const int t0g = q0 + w * 16 + (lane >> 2);
    const int t1g = t0g + 8;
    const float2 gt0 = g_gate[h * SEQ + t0g];
    const float2 gt1 = g_gate[h * SEQ + t1g];

    float m0 = -INFINITY, m1 = -INFINITY, l0 = 0.f, l1 = 0.f;
    float oacc[8][4];
#pragma unroll
    for (int f = 0; f < 8; f++)
#pragma unroll
        for (int e = 0; e < 4; e++) oacc[f][e] = 0.f;

    MBARRIER_WAIT_PARITY(sb, 0);

    for (int i = 0; i < nS; i++) {
        const int stg = i % AKV_STAGES;
        MBARRIER_WAIT_PARITY(sb + 8 + stg * 8, (i / AKV_STAGES) & 1);

        const int s0 = i * AST;
        const uint32_t kb0 = sKV + stg * AKV_BUF;
        const uint32_t kR = kb0, kI = kb0 + AKV_TILE, vT = kb0 + 2 * AKV_TILE;

        float sacc[8][4];
#pragma unroll
        for (int f = 0; f < 8; f++)
#pragma unroll
            for (int e = 0; e < 4; e++) sacc[f][e] = 0.f;

#pragma unroll
        for (int jd = 0; jd < 4; jd++) {
            const uint32_t kb = (uint32_t)(jd * 32);
            const uint32_t offA = SWZ128((uint32_t)((w * 16 + a_row) * 128) + kb + a_cb);
            uint32_t aqr[4], aqi[4];
            ldsm_x4(aqr[0], aqr[1], aqr[2], aqr[3], sQ + offA);
            ldsm_x4(aqi[0], aqi[1], aqi[2], aqi[3], sQ + AQ_TILE + offA);
#pragma unroll
            for (int gp = 0; gp < 2; gp++) {
                uint32_t rf[2][4], imf[2][4];
#pragma unroll
                for (int g2 = 0; g2 < 2; g2++) {
                    const int g = gp * 2 + g2;
                    const uint32_t offB = SWZ128((uint32_t)((g * 16 + b_row) * 128) + kb + b_cb);
                    ldsm_x4(rf[g2][0], rf[g2][1], rf[g2][2], rf[g2][3], kR + offB);
                    ldsm_x4(imf[g2][0], imf[g2][1], imf[g2][2], imf[g2][3], kI + offB);
                }
#pragma unroll
                for (int g2 = 0; g2 < 2; g2++) {
                    const int s2 = 2 * (gp * 2 + g2);
                    mma_fp16(sacc[s2],     aqr, rf[g2][0], rf[g2][1]);
                    mma_fp16(sacc[s2 + 1], aqr, rf[g2][2], rf[g2][3]);
                }
#pragma unroll
                for (int g2 = 0; g2 < 2; g2++) {
                    const int s2 = 2 * (gp * 2 + g2);
                    mma_fp16(sacc[s2],     aqi, imf[g2][0], imf[g2][1]);
                    mma_fp16(sacc[s2 + 1], aqi, imf[g2][2], imf[g2][3]);
                }
            }
        }

        float pm0 = -INFINITY, pm1 = -INFINITY;
#pragma unroll
        for (int f = 0; f < 8; f++) {
            const int sb2 = s0 + f * 8 + (lane & 3) * 2;
            const float2 gs0 = g_gate[h * SEQ + sb2];
            const float2 gs1 = g_gate[h * SEQ + sb2 + 1];
            float v00 = sacc[f][0] * SCALE_F * (gs0.x * gt0.x + gs0.y * gt0.y);
            float v01 = sacc[f][1] * SCALE_F * (gs1.x * gt0.x + gs1.y * gt0.y);
            float v10 = sacc[f][2] * SCALE_F * (gs0.x * gt1.x + gs0.y * gt1.y);
            float v11 = sacc[f][3] * SCALE_F * (gs1.x * gt1.x + gs1.y * gt1.y);
            if (sb2 > t0g)     v00 = -INFINITY;
            if (sb2 + 1 > t0g) v01 = -INFINITY;
            if (sb2 > t1g)     v10 = -INFINITY;
            if (sb2 + 1 > t1g) v11 = -INFINITY;
            sacc[f][0] = v00; sacc[f][1] = v01; sacc[f][2] = v10; sacc[f][3] = v11;
            pm0 = fmaxf(pm0, fmaxf(v00, v01));
            pm1 = fmaxf(pm1, fmaxf(v10, v11));
        }
        pm0 = fmaxf(pm0, __shfl_xor_sync(0xffffffffu, pm0, 1));
        pm0 = fmaxf(pm0, __shfl_xor_sync(0xffffffffu, pm0, 2));
        pm1 = fmaxf(pm1, __shfl_xor_sync(0xffffffffu, pm1, 1));
        pm1 = fmaxf(pm1, __shfl_xor_sync(0xffffffffu, pm1, 2));

        const float mn0 = fmaxf(m0, pm0), mn1 = fmaxf(m1, pm1);
        const float cr0 = __expf(m0 - mn0), cr1 = __expf(m1 - mn1);
        float rs0 = 0.f, rs1 = 0.f;
#pragma unroll
        for (int f = 0; f < 8; f++) {
            sacc[f][0] = __expf(sacc[f][0] - mn0);
            sacc[f][1] = __expf(sacc[f][1] - mn0);
            sacc[f][2] = __expf(sacc[f][2] - mn1);
            sacc[f][3] = __expf(sacc[f][3] - mn1);
            rs0 += sacc[f][0] + sacc[f][1];
            rs1 += sacc[f][2] + sacc[f][3];
        }
        rs0 += __shfl_xor_sync(0xffffffffu, rs0, 1);
        rs0 += __shfl_xor_sync(0xffffffffu, rs0, 2);
        rs1 += __shfl_xor_sync(0xffffffffu, rs1, 1);
        rs1 += __shfl_xor_sync(0xffffffffu, rs1, 2);
        l0 = l0 * cr0 + rs0; m0 = mn0;
        l1 = l1 * cr1 + rs1; m1 = mn1;
#pragma unroll
        for (int f = 0; f < 8; f++) {
            oacc[f][0] *= cr0; oacc[f][1] *= cr0;
            oacc[f][2] *= cr1; oacc[f][3] *= cr1;
        }

#pragma unroll
        for (int j = 0; j < 4; j++) {
            uint32_t ph[4] = {
                pack_half(sacc[2 * j][0],     sacc[2 * j][1]),
                pack_half(sacc[2 * j][2],     sacc[2 * j][3]),
                pack_half(sacc[2 * j + 1][0], sacc[2 * j + 1][1]),
                pack_half(sacc[2 * j + 1][2], sacc[2 * j + 1][3])};
#pragma unroll
            for (int dgp = 0; dgp < 2; dgp++) {
                uint32_t vf[2][4];
#pragma unroll
                for (int d2 = 0; d2 < 2; d2++) {
                    const int dg = dgp * 2 + d2;
                    const uint32_t offV = SWZ128((uint32_t)((16 * j + a_row) * 128) +
                                                 (uint32_t)(dg * 32) + a_cb);
                    ldsm_x4_t(vf[d2][0], vf[d2][1], vf[d2][2], vf[d2][3], vT + offV);
                }
#pragma unroll
                for (int d2 = 0; d2 < 2; d2++) {
                    const int o2 = 2 * (dgp * 2 + d2);
                    mma_fp16(oacc[o2],     ph, vf[d2][0], vf[d2][1]);
                    mma_fp16(oacc[o2 + 1], ph, vf[d2][2], vf[d2][3]);
                }
            }
        }
        __syncthreads();
        if (i + AKV_STAGES < nS && tid == 0) issue_kv(i + AKV_STAGES, stg);
    }

    // epilogue: normalize, write single fp16 in GEMM-A tiled layout
    const float iv0 = 1.0f / l0, iv1 = 1.0f / l1;
#pragma unroll
    for (int f = 0; f < 8; f++) {
        const int d = f * 8 + (lane & 3) * 2;
        size_t off0 = gemmA_off(b * SEQ + t0g, h * 64 + d);
        size_t off1 = gemmA_off(b * SEQ + t1g, h * 64 + d);
        *(uint32_t*)((char*)g_a + off0) = pack_half(oacc[f][0] * iv0, oacc[f][1] * iv0);
        *(uint32_t*)((char*)g_a + off1) = pack_half(oacc[f][2] * iv1, oacc[f][3] * iv1);
    }
}

// ---------------- launch ---------------------------------------------------
extern "C" void kernel_launch(void* const* d_in, const int* in_sizes, int n_in,
                              void* d_out, int out_size) {
    const float* x     = (const float*)d_in[0];
    const float* Wq    = (const float*)d_in[1];
    const float* Wk    = (const float*)d_in[2];
    const float* Wv    = (const float*)d_in[3];
    const float* Wo    = (const float*)d_in[4];
    const float* theta = (const float*)d_in[5];
    float* out = (float*)d_out;

    float *qraw, *kraw, *v;
    __half *xg, *ag, *vv, *wq, *wk, *wv, *wo;
    cudaGetSymbolAddress((void**)&qraw, g_qraw);
    cudaGetSymbolAddress((void**)&kraw, g_kraw);
    cudaGetSymbolAddress((void**)&v,    g_v);
    cudaGetSymbolAddress((void**)&xg,  g_x);
    cudaGetSymbolAddress((void**)&ag,  g_a);
    cudaGetSymbolAddress((void**)&vv,  g_vv);
    cudaGetSymbolAddress((void**)&wq,  g_wq);
    cudaGetSymbolAddress((void**)&wk,  g_wk);
    cudaGetSymbolAddress((void**)&wv,  g_wv);
    cudaGetSymbolAddress((void**)&wo,  g_wo);

    cudaFuncSetAttribute(gemm_qkv,
                         cudaFuncAttributeMaxDynamicSharedMemorySize, GEMM_SMEM);
    cudaFuncSetAttribute(gemm_out,
                         cudaFuncAttributeMaxDynamicSharedMemorySize, GEMM_SMEM);
    cudaFuncSetAttribute(attn_mma,
                         cudaFuncAttributeMaxDynamicSharedMemorySize, ATT_SMEM);

    dim3 tblk(32, 8);

    convert_gemm<<<MROWS * CDIM / 2 / 256, 256>>>(x, xg);
    gate_init<<<HEADS * SEQ / 256, 256>>>(theta);
    transpose_half<<<dim3(2 * CDIM / 32, CDIM / 32), tblk>>>(Wq, wq, CDIM, 2 * CDIM);
    transpose_half<<<dim3(2 * CDIM / 32, CDIM / 32), tblk>>>(Wk, wk, CDIM, 2 * CDIM);
    transpose_half<<<dim3(CDIM / 32, CDIM / 32), tblk>>>(Wv, wv, CDIM, CDIM);
    transpose_half<<<dim3(CDIM / 32, CDIM / 32), tblk>>>(Wo, wo, CDIM, CDIM);

    gemm_qkv<<<dim3(20, MROWS / 128), 256, GEMM_SMEM>>>(
        xg, wq, wk, wv, qraw, kraw, v);

    transform_qk_fp16<<<MROWS * CDIM / 2 / 256, 256>>>();
    convert_att_single<<<MROWS * CDIM / 2 / 256, 256>>>(v, vv);

    attn_mma<<<dim3(SEQ / AQT, HEADS, BATCH), 256, ATT_SMEM>>>();

    gemm_out<<<dim3(CDIM / 256, MROWS / 128), 256, GEMM_SMEM>>>(ag, wo, out, CDIM);
}

// round 14
// speedup vs baseline: 1.9890x; 1.9890x over previous
#include <cuda_runtime.h>
#include <cuda_bf16.h>
#include <cuda_fp16.h>
#include <cstdint>
#include <math.h>

// Problem constants
#define BATCH   2
#define SEQ     2048
#define CDIM    1024
#define HEADS   16
#define HDIM    64
#define GAMMA_F 8.0f
#define SCALE_F 0.125f
#define MROWS   (BATCH*SEQ)          // 4096
#define KDIM    1024

// ---------------- scratch (device globals; no allocation allowed) ----------
__device__ float g_qraw[MROWS * 2 * CDIM];
__device__ float g_kraw[MROWS * 2 * CDIM];
__device__ float g_v   [MROWS * CDIM];

// fp16 GEMM operands (pre-swizzled tile-blocked layouts) -- ALL single fp16
__device__ __half g_x  [MROWS * CDIM];
__device__ __half g_a  [MROWS * CDIM];
__device__ __half g_wq [2 * CDIM * CDIM];
__device__ __half g_wk [2 * CDIM * CDIM];
__device__ __half g_wv [CDIM * CDIM];
__device__ __half g_wo [CDIM * CDIM];

// attention operands: ALL single fp16
__device__ __half g_qr [MROWS * CDIM];
__device__ __half g_qi [MROWS * CDIM];
__device__ __half g_kr [MROWS * CDIM];
__device__ __half g_ki [MROWS * CDIM];
__device__ __half g_vv [MROWS * CDIM];
__device__ float2 g_gate[HEADS * SEQ];

// ---------------- helpers ---------------------------------------------------
__device__ __forceinline__ uint32_t smem_u32(const void* p) {
    uint32_t a;
    asm("{ .reg .u64 t; cvta.to.shared.u64 t, %1; cvt.u32.u64 %0, t; }"
        : "=r"(a) : "l"(p));
    return a;
}
#define SWZ128(o) ((o) ^ (((o) >> 3) & 0x70))

__device__ __forceinline__ size_t gemmA_off(int row, int col) {
    return ((size_t)((row >> 7) * 16 + (col >> 6)) << 14) +
           SWZ128((uint32_t)((row & 127) * 128 + (col & 63) * 2));
}
__device__ __forceinline__ size_t att_off(int b, int h, int t, int d) {
    return ((size_t)((b * HEADS + h) * 32 + (t >> 6)) << 13) +
           SWZ128((uint32_t)((t & 63) * 128 + d * 2));
}

#define MBARRIER_INIT(mbar, count) \
    asm volatile("mbarrier.init.shared.b64 [%0], %1;" :: "r"((uint32_t)(mbar)), "r"((uint32_t)(count)) : "memory")
#define MBAR_EXPECT(mbar, bytes) \
    asm volatile("mbarrier.arrive.expect_tx.shared.b64 _, [%0], %1;" :: "r"((uint32_t)(mbar)), "r"((uint32_t)(bytes)) : "memory")

#define MBARRIER_WAIT_PARITY(mbar, parity) do { \
    uint32_t _m = (uint32_t)(mbar); uint32_t _p = (uint32_t)(parity); uint32_t _d; \
    asm volatile("{\n\t.reg .pred p;\n\t" \
        "mbarrier.try_wait.parity.acquire.cta.shared::cta.b64 p, [%1], %2;\n\t" \
        "selp.b32 %0, 1, 0, p;\n\t}" : "=r"(_d) : "r"(_m), "r"(_p) : "memory"); \
    if (!_d) { \
        asm volatile("{\n\t.reg .pred P1;\n\t" \
            "WL_%=:\n\t" \
            "mbarrier.try_wait.parity.acquire.cta.shared::cta.b64 P1, [%0], %1, 0x989680;\n\t" \
            "@P1 bra.uni WD_%=;\n\tbra.uni WL_%=;\n\tWD_%=:\n\t}" \
            :: "r"(_m), "r"(_p) : "memory"); \
    } } while (0)

__device__ __forceinline__ void bulk_g2s(uint32_t dst, const void* src,
                                         uint32_t bytes, uint32_t mbar) {
    asm volatile(
        "cp.async.bulk.shared::cluster.global.mbarrier::complete_tx::bytes [%0], [%1], %2, [%3];"
        :: "r"(dst), "l"(src), "r"(bytes), "r"(mbar) : "memory");
}

__device__ __forceinline__ void ldsm_x4(uint32_t& r0, uint32_t& r1,
                                        uint32_t& r2, uint32_t& r3, uint32_t addr) {
    asm volatile("ldmatrix.sync.aligned.m8n8.x4.shared.b16 {%0,%1,%2,%3}, [%4];"
                 : "=r"(r0), "=r"(r1), "=r"(r2), "=r"(r3) : "r"(addr));
}
__device__ __forceinline__ void ldsm_x4_t(uint32_t& r0, uint32_t& r1,
                                          uint32_t& r2, uint32_t& r3, uint32_t addr) {
    asm volatile("ldmatrix.sync.aligned.m8n8.x4.trans.shared.b16 {%0,%1,%2,%3}, [%4];"
                 : "=r"(r0), "=r"(r1), "=r"(r2), "=r"(r3) : "r"(addr));
}

__device__ __forceinline__ void mma_fp16(float* c, const uint32_t* a,
                                         uint32_t b0, uint32_t b1) {
    asm volatile(
        "mma.sync.aligned.m16n8k16.row.col.f32.f16.f16.f32 "
        "{%0,%1,%2,%3}, {%4,%5,%6,%7}, {%8,%9}, {%0,%1,%2,%3};"
        : "+f"(c[0]), "+f"(c[1]), "+f"(c[2]), "+f"(c[3])
        : "r"(a[0]), "r"(a[1]), "r"(a[2]), "r"(a[3]), "r"(b0), "r"(b1));
}

__device__ __forceinline__ uint32_t pack_half(float a, float b) {
    __half2 t = __floats2half2_rn(a, b);
    return *reinterpret_cast<uint32_t*>(&t);
}

// ---------------- single-fp16 GEMM: C = A[M,K] * B[N,K]^T -------------------
// Block 128x256, 8 warps 64x64, K-chunk 64, 3-stage bulk pipeline, 1-MMA pass.
// 1 CTA/SM (244 regs -- accumulator alone is 128 regs; occ=2 would spill).
#define BK       64
#define NCH      (KDIM / BK)
#define A_TB     16384
#define STG_B    (3 * A_TB)              // A, B0, B1 = 49152
#define GSTAGES  3
#define GEMM_SMEM (1024 + GSTAGES * STG_B)  // 148480

__device__ __forceinline__ void gemm_body(
    const char* cA, const char* cB, int mb, int nb, float acc[4][8][4]) {
    extern __shared__ char smem[];
    const uint32_t sb = smem_u32(smem);
    const int tid = threadIdx.x, wid = tid >> 5, lane = tid & 31;
    const int wm = (wid & 1) * 64;
    const int wn = (wid >> 1) * 64;

    const size_t mbB = ((size_t)mb * 16) << 14;
    const size_t nbB0 = ((size_t)(nb * 2) * 16) << 14;
    const size_t nbB1 = ((size_t)(nb * 2 + 1) * 16) << 14;

    if (tid == 0) {
        MBARRIER_INIT(sb, 1); MBARRIER_INIT(sb + 8, 1); MBARRIER_INIT(sb + 16, 1);
    }
    __syncthreads();

    auto issue = [&](int chunk, int buf) {
        const uint32_t st = sb + 1024 + buf * STG_B;
        const uint32_t bar = sb + buf * 8;
        const size_t kB = ((size_t)chunk) << 14;
        MBAR_EXPECT(bar, STG_B);
        bulk_g2s(st,            cA + mbB + kB,   A_TB, bar);
        bulk_g2s(st + A_TB,     cB + nbB0 + kB,  A_TB, bar);
        bulk_g2s(st + 2 * A_TB, cB + nbB1 + kB,  A_TB, bar);
    };

    if (tid == 0) { issue(0, 0); issue(1, 1); issue(2, 2); }

#pragma unroll
    for (int i = 0; i < 4; i++)
#pragma unroll
        for (int j = 0; j < 8; j++)
#pragma unroll
            for (int e = 0; e < 4; e++) acc[i][j][e] = 0.f;

    const int a_row = (lane & 15);
    const uint32_t a_cb = (uint32_t)((lane >> 4) * 16);
    const int b_row = ((lane >> 4) & 1) * 8 + (lane & 7);
    const uint32_t b_cb = (uint32_t)(((lane >> 3) & 1) * 16);

    for (int i = 0; i < NCH; i++) {
        const int stg = i % GSTAGES;
        MBARRIER_WAIT_PARITY(sb + stg * 8, (i / GSTAGES) & 1);

        const uint32_t st = sb + 1024 + stg * STG_B;
        const uint32_t aA = st;
        const uint32_t bB = st + A_TB;     // 256 rows contiguous

#pragma unroll
        for (int ks = 0; ks < 4; ks++) {
            const uint32_t kb = (uint32_t)(ks * 32);
            uint32_t af[4][4];
#pragma unroll
            for (int mi = 0; mi < 4; mi++) {
                uint32_t off = SWZ128((uint32_t)((wm + mi * 16 + a_row) * 128) + kb + a_cb);
                ldsm_x4(af[mi][0], af[mi][1], af[mi][2], af[mi][3], aA + off);
            }
#pragma unroll
            for (int hb = 0; hb < 2; hb++) {
                uint32_t bf[2][4];
#pragma unroll
                for (int g2 = 0; g2 < 2; g2++) {
                    const int ng = hb * 2 + g2;
                    uint32_t off = SWZ128((uint32_t)((wn + ng * 16 + b_row) * 128) + kb + b_cb);
                    ldsm_x4(bf[g2][0], bf[g2][1], bf[g2][2], bf[g2][3], bB + off);
                }
#pragma unroll
                for (int g2 = 0; g2 < 2; g2++)
#pragma unroll
                    for (int mi = 0; mi < 4; mi++) {
                        const int nj = 2 * (hb * 2 + g2);
                        mma_fp16(acc[mi][nj],     af[mi], bf[g2][0], bf[g2][1]);
                        mma_fp16(acc[mi][nj + 1], af[mi], bf[g2][2], bf[g2][3]);
                    }
            }
        }
        __syncthreads();
        if (i + GSTAGES < NCH && tid == 0) issue(i + GSTAGES, stg);
    }
}

__device__ __forceinline__ void gemm_store(float acc[4][8][4], float* Cm, int N,
                                           int m0, int n0) {
    const int tid = threadIdx.x, wid = tid >> 5, lane = tid & 31;
    const int wm = (wid & 1) * 64, wn = (wid >> 1) * 64;
    const int cr = lane >> 2;
    const int cc = (lane & 3) * 2;
#pragma unroll
    for (int mi = 0; mi < 4; mi++) {
#pragma unroll
        for (int nj = 0; nj < 8; nj++) {
            const int r = m0 + wm + mi * 16 + cr;
            const int c = n0 + wn + nj * 8 + cc;
            *(float2*)&Cm[(size_t)r * N + c] = make_float2(acc[mi][nj][0], acc[mi][nj][1]);
            *(float2*)&Cm[(size_t)(r + 8) * N + c] = make_float2(acc[mi][nj][2], acc[mi][nj][3]);
        }
    }
}

// Combined Q/K/V projection GEMM: grid.x = 20 (8 Q | 8 K | 4 V), grid.y = 32
__global__ __launch_bounds__(256, 1)
void gemm_qkv(const __half* __restrict__ x,
              const __half* __restrict__ wq, const __half* __restrict__ wk,
              const __half* __restrict__ wv,
              float* __restrict__ qraw, float* __restrict__ kraw, float* __restrict__ vout) {
    const int nx = blockIdx.x;
    const __half* B;
    float* Cm;
    int N, nb;
    if (nx < 8)       { B = wq; Cm = qraw; N = 2 * CDIM; nb = nx; }
    else if (nx < 16) { B = wk; Cm = kraw; N = 2 * CDIM; nb = nx - 8; }
    else              { B = wv; Cm = vout; N = CDIM;     nb = nx - 16; }

    float acc[4][8][4];
    gemm_body((const char*)x, (const char*)B, blockIdx.y, nb, acc);
    gemm_store(acc, Cm, N, blockIdx.y * 128, nb * 256);
}

// Output projection GEMM
__global__ __launch_bounds__(256, 1)
void gemm_out(const __half* __restrict__ A, const __half* __restrict__ B,
              float* __restrict__ Cm, int N) {
    float acc[4][8][4];
    gemm_body((const char*)A, (const char*)B, blockIdx.y, blockIdx.x, acc);
    gemm_store(acc, Cm, N, blockIdx.y * 128, blockIdx.x * 256);
}

// ---------------- fp32 -> single fp16, GEMM-A tiled layout ------------------
__global__ __launch_bounds__(256)
void convert_gemm(const float* __restrict__ src, __half* __restrict__ dst) {
    int i2 = blockIdx.x * 256 + threadIdx.x;
    int row = i2 >> 9, col = (i2 & 511) * 2;
    float2 v = *(const float2*)&src[(size_t)row * CDIM + col];
    size_t off = gemmA_off(row, col);
    *(uint32_t*)((char*)dst + off) = pack_half(v.x, v.y);
}

// fp32 -> single fp16 in ATTENTION tiled layout (for V)
__global__ __launch_bounds__(256)
void convert_att_single(const float* __restrict__ src, __half* __restrict__ dst) {
    int i2 = blockIdx.x * 256 + threadIdx.x;
    int bt = i2 >> 9, col = (i2 & 511) * 2;
    int b = bt >> 11, t = bt & (SEQ - 1);
    int h = col >> 6, d = col & 63;
    float2 v = *(const float2*)&src[(size_t)bt * CDIM + col];
    size_t off = att_off(b, h, t, d);
    *(uint32_t*)((char*)dst + off) = pack_half(v.x, v.y);
}

// ---------------- weight transpose -> single fp16, GEMM-A tiled layout ------
__global__ __launch_bounds__(256)
void transpose_half(const float* __restrict__ W, __half* __restrict__ Hh,
                    int K, int N) {
    __shared__ float t[32][33];
    const int tx = threadIdx.x, ty = threadIdx.y;
    const int n0 = blockIdx.x * 32, k0 = blockIdx.y * 32;
#pragma unroll
    for (int i = 0; i < 32; i += 8)
        t[ty + i][tx] = W[(size_t)(k0 + ty + i) * N + n0 + tx];
    __syncthreads();
#pragma unroll
    for (int i = 0; i < 32; i += 8) {
        float v = t[tx][ty + i];
        size_t off = gemmA_off(n0 + ty + i, k0 + tx);
        *(__half*)((char*)Hh + off) = __float2half(v);
    }
}

// ---------------- amp/phase transform -> single fp16 ------------------------
__device__ __forceinline__ float softplus_f(float a) {
    return (a > 20.f) ? a : log1pf(expf(a));
}

__global__ __launch_bounds__(256)
void transform_qk_fp16() {
    int i2 = blockIdx.x * 256 + threadIdx.x;
    int c2 = i2 * 2;
    int bt = c2 >> 10;
    int c  = c2 & 1023;
    int b = bt >> 11, t = bt & (SEQ - 1);
    int h = c >> 6, d = c & 63;
    size_t rbase = (size_t)bt * (2 * CDIM);
    size_t off = att_off(b, h, t, d);

    float qa0 = g_qraw[rbase + c],        qa1 = g_qraw[rbase + c + 1];
    float qp0 = g_qraw[rbase + CDIM + c], qp1 = g_qraw[rbase + CDIM + c + 1];
    float ka0 = g_kraw[rbase + c],        ka1 = g_kraw[rbase + c + 1];
    float kp0 = g_kraw[rbase + CDIM + c], kp1 = g_kraw[rbase + CDIM + c + 1];

    float qs0 = softplus_f(qa0), qs1 = softplus_f(qa1);
    float ks0 = softplus_f(ka0), ks1 = softplus_f(ka1);
    float s0, c0, s1, c1, s2, c2f, s3, c3;
    sincosf(qp0, &s0, &c0); sincosf(qp1, &s1, &c1);
    sincosf(kp0, &s2, &c2f); sincosf(kp1, &s3, &c3);

    *(uint32_t*)((char*)g_qr + off) = pack_half(qs0 * c0, qs1 * c1);
    *(uint32_t*)((char*)g_qi + off) = pack_half(qs0 * s0, qs1 * s1);
    *(uint32_t*)((char*)g_kr + off) = pack_half(ks0 * c2f, ks1 * c3);
    *(uint32_t*)((char*)g_ki + off) = pack_half(ks0 * s2, ks1 * s3);
}

__global__ void gate_init(const float* __restrict__ theta) {
    int i = blockIdx.x * 256 + threadIdx.x;
    int h = i >> 11, s = i & (SEQ - 1);
    float th = theta[h] * (1.0f / GAMMA_F);
    float sn, cs;
    sincosf(th * (float)s, &sn, &cs);
    g_gate[i] = make_float2(cs, sn);
}

// ---------------- fully fp16 flash attention with moiré gate ----------------
#define AQT 128
#define AST 64
#define AQ_TILE 16384
#define AKV_TILE 8192
#define AKV_BUF (3 * AKV_TILE)              // 24576
#define AKV_STAGES 4
#define ATT_SMEM (1024 + 2 * AQ_TILE + AKV_STAGES * AKV_BUF)  // 132096

__global__ __launch_bounds__(256)
void attn_mma() {
    extern __shared__ char smem[];
    const uint32_t sb = smem_u32(smem);
    const uint32_t sQ  = sb + 1024;
    const uint32_t sKV = sQ + 2 * AQ_TILE;

    const int tid = threadIdx.x, w = tid >> 5, lane = tid & 31;
    const int q0 = (int)(gridDim.x - 1 - blockIdx.x) * AQT;
    const int h = blockIdx.y, b = blockIdx.z;
    const int nS = q0 / AST + 2;

    const size_t bhB = ((size_t)((b * HEADS + h) * 32)) << 13;

    if (tid == 0) {
        MBARRIER_INIT(sb, 1);
#pragma unroll
        for (int s = 0; s < AKV_STAGES; s++) MBARRIER_INIT(sb + 8 + s * 8, 1);
    }
    __syncthreads();

    auto issue_kv = [&](int chunk, int buf) {
        const uint32_t st = sKV + buf * AKV_BUF;
        const uint32_t bar = sb + 8 + buf * 8;
        const size_t src = bhB + (((size_t)chunk) << 13);
        MBAR_EXPECT(bar, AKV_BUF);
        bulk_g2s(st,                (const char*)g_kr + src, AKV_TILE, bar);
        bulk_g2s(st + AKV_TILE,     (const char*)g_ki + src, AKV_TILE, bar);
        bulk_g2s(st + 2 * AKV_TILE, (const char*)g_vv + src, AKV_TILE, bar);
    };

    if (tid == 0) {
        const size_t qsrc = bhB + (((size_t)(q0 >> 6)) << 13);
        MBAR_EXPECT(sb, 2 * AQ_TILE);
        bulk_g2s(sQ,           (const char*)g_qr + qsrc, AQ_TILE, sb);
        bulk_g2s(sQ + AQ_TILE, (const char*)g_qi + qsrc, AQ_TILE, sb);
#pragma unroll
        for (int c = 0; c < AKV_STAGES; c++)
            if (c < nS) issue_kv(c, c);
    }

    const int a_row = lane & 15;
    const uint32_t a_cb = (uint32_t)((lane >> 4) * 16);
    const int b_row = ((lane >> 4) & 1) * 8 + (lane & 7);
    const uint32_t b_cb = (uint32_t)(((lane >> 3) & 1) * 16);

    const int t0g = q0 + w * 16 + (lane >> 2);
    const int t1g = t0g + 8;
    const float2 gt0 = g_gate[h * SEQ + t0g];
    const float2 gt1 = g_gate[h * SEQ + t1g];

    float m0 = -INFINITY, m1 = -INFINITY, l0 = 0.f, l1 = 0.f;
    float oacc[8][4];
#pragma unroll
    for (int f = 0; f < 8; f++)
#pragma unroll
        for (int e = 0; e < 4; e++) oacc[f][e] = 0.f;

    MBARRIER_WAIT_PARITY(sb, 0);

    for (int i = 0; i < nS; i++) {
        const int stg = i % AKV_STAGES;
        MBARRIER_WAIT_PARITY(sb + 8 + stg * 8, (i / AKV_STAGES) & 1);

        const int s0 = i * AST;
        const uint32_t kb0 = sKV + stg * AKV_BUF;
        const uint32_t kR = kb0, kI = kb0 + AKV_TILE, vT = kb0 + 2 * AKV_TILE;

        float sacc[8][4];
#pragma unroll
        for (int f = 0; f < 8; f++)
#pragma unroll
            for (int e = 0; e < 4; e++) sacc[f][e] = 0.f;

#pragma unroll
        for (int jd = 0; jd < 4; jd++) {
            const uint32_t kb = (uint32_t)(jd * 32);
            const uint32_t offA = SWZ128((uint32_t)((w * 16 + a_row) * 128) + kb + a_cb);
            uint32_t aqr[4], aqi[4];
            ldsm_x4(aqr[0], aqr[1], aqr[2], aqr[3], sQ + offA);
            ldsm_x4(aqi[0], aqi[1], aqi[2], aqi[3], sQ + AQ_TILE + offA);
#pragma unroll
            for (int gp = 0; gp < 2; gp++) {
                uint32_t rf[2][4], imf[2][4];
#pragma unroll
                for (int g2 = 0; g2 < 2; g2++) {
                    const int g = gp * 2 + g2;
                    const uint32_t offB = SWZ128((uint32_t)((g * 16 + b_row) * 128) + kb + b_cb);
                    ldsm_x4(rf[g2][0], rf[g2][1], rf[g2][2], rf[g2][3], kR + offB);
                    ldsm_x4(imf[g2][0], imf[g2][1], imf[g2][2], imf[g2][3], kI + offB);
                }
#pragma unroll
                for (int g2 = 0; g2 < 2; g2++) {
                    const int s2 = 2 * (gp * 2 + g2);
                    mma_fp16(sacc[s2],     aqr, rf[g2][0], rf[g2][1]);
                    mma_fp16(sacc[s2 + 1], aqr, rf[g2][2], rf[g2][3]);
                }
#pragma unroll
                for (int g2 = 0; g2 < 2; g2++) {
                    const int s2 = 2 * (gp * 2 + g2);
                    mma_fp16(sacc[s2],     aqi, imf[g2][0], imf[g2][1]);
                    mma_fp16(sacc[s2 + 1], aqi, imf[g2][2], imf[g2][3]);
                }
            }
        }

        float pm0 = -INFINITY, pm1 = -INFINITY;
#pragma unroll
        for (int f = 0; f < 8; f++) {
            const int sb2 = s0 + f * 8 + (lane & 3) * 2;
            const float2 gs0 = g_gate[h * SEQ + sb2];
            const float2 gs1 = g_gate[h * SEQ + sb2 + 1];
            float v00 = sacc[f][0] * SCALE_F * (gs0.x * gt0.x + gs0.y * gt0.y);
            float v01 = sacc[f][1] * SCALE_F * (gs1.x * gt0.x + gs1.y * gt0.y);
            float v10 = sacc[f][2] * SCALE_F * (gs0.x * gt1.x + gs0.y * gt1.y);
            float v11 = sacc[f][3] * SCALE_F * (gs1.x * gt1.x + gs1.y * gt1.y);
            if (sb2 > t0g)     v00 = -INFINITY;
            if (sb2 + 1 > t0g) v01 = -INFINITY;
            if (sb2 > t1g)     v10 = -INFINITY;
            if (sb2 + 1 > t1g) v11 = -INFINITY;
            sacc[f][0] = v00; sacc[f][1] = v01; sacc[f][2] = v10; sacc[f][3] = v11;
            pm0 = fmaxf(pm0, fmaxf(v00, v01));
            pm1 = fmaxf(pm1, fmaxf(v10, v11));
        }
        pm0 = fmaxf(pm0, __shfl_xor_sync(0xffffffffu, pm0, 1));
        pm0 = fmaxf(pm0, __shfl_xor_sync(0xffffffffu, pm0, 2));
        pm1 = fmaxf(pm1, __shfl_xor_sync(0xffffffffu, pm1, 1));
        pm1 = fmaxf(pm1, __shfl_xor_sync(0xffffffffu, pm1, 2));

        const float mn0 = fmaxf(m0, pm0), mn1 = fmaxf(m1, pm1);
        const float cr0 = __expf(m0 - mn0), cr1 = __expf(m1 - mn1);
        float rs0 = 0.f, rs1 = 0.f;
#pragma unroll
        for (int f = 0; f < 8; f++) {
            sacc[f][0] = __expf(sacc[f][0] - mn0);
            sacc[f][1] = __expf(sacc[f][1] - mn0);
            sacc[f][2] = __expf(sacc[f][2] - mn1);
            sacc[f][3] = __expf(sacc[f][3] - mn1);
            rs0 += sacc[f][0] + sacc[f][1];
            rs1 += sacc[f][2] + sacc[f][3];
        }
        rs0 += __shfl_xor_sync(0xffffffffu, rs0, 1);
        rs0 += __shfl_xor_sync(0xffffffffu, rs0, 2);
        rs1 += __shfl_xor_sync(0xffffffffu, rs1, 1);
        rs1 += __shfl_xor_sync(0xffffffffu, rs1, 2);
        l0 = l0 * cr0 + rs0; m0 = mn0;
        l1 = l1 * cr1 + rs1; m1 = mn1;
#pragma unroll
        for (int f = 0; f < 8; f++) {
            oacc[f][0] *= cr0; oacc[f][1] *= cr0;
            oacc[f][2] *= cr1; oacc[f][3] *= cr1;
        }

#pragma unroll
        for (int j = 0; j < 4; j++) {
            uint32_t ph[4] = {
                pack_half(sacc[2 * j][0],     sacc[2 * j][1]),
                pack_half(sacc[2 * j][2],     sacc[2 * j][3]),
                pack_half(sacc[2 * j + 1][0], sacc[2 * j + 1][1]),
                pack_half(sacc[2 * j + 1][2], sacc[2 * j + 1][3])};
#pragma unroll
            for (int dgp = 0; dgp < 2; dgp++) {
                uint32_t vf[2][4];
#pragma unroll
                for (int d2 = 0; d2 < 2; d2++) {
                    const int dg = dgp * 2 + d2;
                    const uint32_t offV = SWZ128((uint32_t)((16 * j + a_row) * 128) +
                                                 (uint32_t)(dg * 32) + a_cb);
                    ldsm_x4_t(vf[d2][0], vf[d2][1], vf[d2][2], vf[d2][3], vT + offV);
                }
#pragma unroll
                for (int d2 = 0; d2 < 2; d2++) {
                    const int o2 = 2 * (dgp * 2 + d2);
                    mma_fp16(oacc[o2],     ph, vf[d2][0], vf[d2][1]);
                    mma_fp16(oacc[o2 + 1], ph, vf[d2][2], vf[d2][3]);
                }
            }
        }
        __syncthreads();
        if (i + AKV_STAGES < nS && tid == 0) issue_kv(i + AKV_STAGES, stg);
    }

    // epilogue: normalize, write single fp16 in GEMM-A tiled layout
    const float iv0 = 1.0f / l0, iv1 = 1.0f / l1;
#pragma unroll
    for (int f = 0; f < 8; f++) {
        const int d = f * 8 + (lane & 3) * 2;
        size_t off0 = gemmA_off(b * SEQ + t0g, h * 64 + d);
        size_t off1 = gemmA_off(b * SEQ + t1g, h * 64 + d);
        *(uint32_t*)((char*)g_a + off0) = pack_half(oacc[f][0] * iv0, oacc[f][1] * iv0);
        *(uint32_t*)((char*)g_a + off1) = pack_half(oacc[f][2] * iv1, oacc[f][3] * iv1);
    }
}

// ---------------- launch ---------------------------------------------------
extern "C" void kernel_launch(void* const* d_in, const int* in_sizes, int n_in,
                              void* d_out, int out_size) {
    const float* x     = (const float*)d_in[0];
    const float* Wq    = (const float*)d_in[1];
    const float* Wk    = (const float*)d_in[2];
    const float* Wv    = (const float*)d_in[3];
    const float* Wo    = (const float*)d_in[4];
    const float* theta = (const float*)d_in[5];
    float* out = (float*)d_out;

    float *qraw, *kraw, *v;
    __half *xg, *ag, *vv, *wq, *wk, *wv, *wo;
    cudaGetSymbolAddress((void**)&qraw, g_qraw);
    cudaGetSymbolAddress((void**)&kraw, g_kraw);
    cudaGetSymbolAddress((void**)&v,    g_v);
    cudaGetSymbolAddress((void**)&xg,  g_x);
    cudaGetSymbolAddress((void**)&ag,  g_a);
    cudaGetSymbolAddress((void**)&vv,  g_vv);
    cudaGetSymbolAddress((void**)&wq,  g_wq);
    cudaGetSymbolAddress((void**)&wk,  g_wk);
    cudaGetSymbolAddress((void**)&wv,  g_wv);
    cudaGetSymbolAddress((void**)&wo,  g_wo);

    cudaFuncSetAttribute(gemm_qkv,
                         cudaFuncAttributeMaxDynamicSharedMemorySize, GEMM_SMEM);
    cudaFuncSetAttribute(gemm_out,
                         cudaFuncAttributeMaxDynamicSharedMemorySize, GEMM_SMEM);
    cudaFuncSetAttribute(attn_mma,
                         cudaFuncAttributeMaxDynamicSharedMemorySize, ATT_SMEM);

    dim3 tblk(32, 8);

    convert_gemm<<<MROWS * CDIM / 2 / 256, 256>>>(x, xg);
    gate_init<<<HEADS * SEQ / 256, 256>>>(theta);
    transpose_half<<<dim3(2 * CDIM / 32, CDIM / 32), tblk>>>(Wq, wq, CDIM, 2 * CDIM);
    transpose_half<<<dim3(2 * CDIM / 32, CDIM / 32), tblk>>>(Wk, wk, CDIM, 2 * CDIM);
    transpose_half<<<dim3(CDIM / 32, CDIM / 32), tblk>>>(Wv, wv, CDIM, CDIM);
    transpose_half<<<dim3(CDIM / 32, CDIM / 32), tblk>>>(Wo, wo, CDIM, CDIM);

    gemm_qkv<<<dim3(20, MROWS / 128), 256, GEMM_SMEM>>>(
        xg, wq, wk, wv, qraw, kraw, v);

    transform_qk_fp16<<<MROWS * CDIM / 2 / 256, 256>>>();
    convert_att_single<<<MROWS * CDIM / 2 / 256, 256>>>(v, vv);

    attn_mma<<<dim3(SEQ / AQT, HEADS, BATCH), 256, ATT_SMEM>>>();

    gemm_out<<<dim3(CDIM / 256, MROWS / 128), 256, GEMM_SMEM>>>(ag, wo, out, CDIM);
}

// round 15
// speedup vs baseline: 2.0759x; 1.0437x over previous
#include <cuda_runtime.h>
#include <cuda_bf16.h>
#include <cuda_fp16.h>
#include <cstdint>
#include <math.h>

// Problem constants
#define BATCH   2
#define SEQ     2048
#define CDIM    1024
#define HEADS   16
#define HDIM    64
#define GAMMA_F 8.0f
#define SCALE_F 0.125f
#define MROWS   (BATCH*SEQ)          // 4096
#define KDIM    1024

// ---------------- scratch (device globals; no allocation allowed) ----------
__device__ __half g_qraw[MROWS * 2 * CDIM];   // fp16 raw projections
__device__ __half g_kraw[MROWS * 2 * CDIM];
__device__ __half g_vraw[MROWS * CDIM];

// fp16 GEMM operands (pre-swizzled tile-blocked layouts) -- ALL single fp16
__device__ __half g_x  [MROWS * CDIM];
__device__ __half g_a  [MROWS * CDIM];
__device__ __half g_wq [2 * CDIM * CDIM];
__device__ __half g_wk [2 * CDIM * CDIM];
__device__ __half g_wv [CDIM * CDIM];
__device__ __half g_wo [CDIM * CDIM];

// attention operands: ALL single fp16
__device__ __half g_qr [MROWS * CDIM];
__device__ __half g_qi [MROWS * CDIM];
__device__ __half g_kr [MROWS * CDIM];
__device__ __half g_ki [MROWS * CDIM];
__device__ __half g_vv [MROWS * CDIM];
__device__ float2 g_gate[HEADS * SEQ];

// ---------------- helpers ---------------------------------------------------
__device__ __forceinline__ uint32_t smem_u32(const void* p) {
    uint32_t a;
    asm("{ .reg .u64 t; cvta.to.shared.u64 t, %1; cvt.u32.u64 %0, t; }"
        : "=r"(a) : "l"(p));
    return a;
}
#define SWZ128(o) ((o) ^ (((o) >> 3) & 0x70))

__device__ __forceinline__ size_t gemmA_off(int row, int col) {
    return ((size_t)((row >> 7) * 16 + (col >> 6)) << 14) +
           SWZ128((uint32_t)((row & 127) * 128 + (col & 63) * 2));
}
__device__ __forceinline__ size_t att_off(int b, int h, int t, int d) {
    return ((size_t)((b * HEADS + h) * 32 + (t >> 6)) << 13) +
           SWZ128((uint32_t)((t & 63) * 128 + d * 2));
}

#define MBARRIER_INIT(mbar, count) \
    asm volatile("mbarrier.init.shared.b64 [%0], %1;" :: "r"((uint32_t)(mbar)), "r"((uint32_t)(count)) : "memory")
#define MBAR_EXPECT(mbar, bytes) \
    asm volatile("mbarrier.arrive.expect_tx.shared.b64 _, [%0], %1;" :: "r"((uint32_t)(mbar)), "r"((uint32_t)(bytes)) : "memory")

#define MBARRIER_WAIT_PARITY(mbar, parity) do { \
    uint32_t _m = (uint32_t)(mbar); uint32_t _p = (uint32_t)(parity); uint32_t _d; \
    asm volatile("{\n\t.reg .pred p;\n\t" \
        "mbarrier.try_wait.parity.acquire.cta.shared::cta.b64 p, [%1], %2;\n\t" \
        "selp.b32 %0, 1, 0, p;\n\t}" : "=r"(_d) : "r"(_m), "r"(_p) : "memory"); \
    if (!_d) { \
        asm volatile("{\n\t.reg .pred P1;\n\t" \
            "WL_%=:\n\t" \
            "mbarrier.try_wait.parity.acquire.cta.shared::cta.b64 P1, [%0], %1, 0x989680;\n\t" \
            "@P1 bra.uni WD_%=;\n\tbra.uni WL_%=;\n\tWD_%=:\n\t}" \
            :: "r"(_m), "r"(_p) : "memory"); \
    } } while (0)

__device__ __forceinline__ void bulk_g2s(uint32_t dst, const void* src,
                                         uint32_t bytes, uint32_t mbar) {
    asm volatile(
        "cp.async.bulk.shared::cluster.global.mbarrier::complete_tx::bytes [%0], [%1], %2, [%3];"
        :: "r"(dst), "l"(src), "r"(bytes), "r"(mbar) : "memory");
}

__device__ __forceinline__ void ldsm_x4(uint32_t& r0, uint32_t& r1,
                                        uint32_t& r2, uint32_t& r3, uint32_t addr) {
    asm volatile("ldmatrix.sync.aligned.m8n8.x4.shared.b16 {%0,%1,%2,%3}, [%4];"
                 : "=r"(r0), "=r"(r1), "=r"(r2), "=r"(r3) : "r"(addr));
}
__device__ __forceinline__ void ldsm_x4_t(uint32_t& r0, uint32_t& r1,
                                          uint32_t& r2, uint32_t& r3, uint32_t addr) {
    asm volatile("ldmatrix.sync.aligned.m8n8.x4.trans.shared.b16 {%0,%1,%2,%3}, [%4];"
                 : "=r"(r0), "=r"(r1), "=r"(r2), "=r"(r3) : "r"(addr));
}

__device__ __forceinline__ void mma_fp16(float* c, const uint32_t* a,
                                         uint32_t b0, uint32_t b1) {
    asm volatile(
        "mma.sync.aligned.m16n8k16.row.col.f32.f16.f16.f32 "
        "{%0,%1,%2,%3}, {%4,%5,%6,%7}, {%8,%9}, {%0,%1,%2,%3};"
        : "+f"(c[0]), "+f"(c[1]), "+f"(c[2]), "+f"(c[3])
        : "r"(a[0]), "r"(a[1]), "r"(a[2]), "r"(a[3]), "r"(b0), "r"(b1));
}

__device__ __forceinline__ uint32_t pack_half(float a, float b) {
    __half2 t = __floats2half2_rn(a, b);
    return *reinterpret_cast<uint32_t*>(&t);
}

// ---------------- single-fp16 GEMM: C = A[M,K] * B[N,K]^T -------------------
// Block 128x256, 8 warps 64x64, K-chunk 128 (two 64-col blocks, contiguous in
// the tiled layout), 2-stage bulk pipeline, 1 MMA pass. 1 CTA/SM (244 regs).
#define BK       128
#define NCH      (KDIM / BK)             // 8
#define A_CHK    32768                   // 128 rows x 2 kc-blocks
#define STG_B    (3 * A_CHK)             // A + B0 + B1 = 98304
#define GSTAGES  2
#define GEMM_SMEM (1024 + GSTAGES * STG_B)  // 197632

__device__ __forceinline__ void gemm_body(
    const char* cA, const char* cB, int mb, int nb, float acc[4][8][4]) {
    extern __shared__ char smem[];
    const uint32_t sb = smem_u32(smem);
    const int tid = threadIdx.x, wid = tid >> 5, lane = tid & 31;
    const int wm = (wid & 1) * 64;
    const int wn = (wid >> 1) * 64;

    const size_t mbB  = ((size_t)mb * 16) << 14;             // 256KB row-blocks
    const size_t nbB0 = ((size_t)(nb * 2) * 16) << 14;
    const size_t nbB1 = ((size_t)(nb * 2 + 1) * 16) << 14;

    if (tid == 0) { MBARRIER_INIT(sb, 1); MBARRIER_INIT(sb + 8, 1); }
    __syncthreads();

    auto issue = [&](int chunk, int buf) {
        const uint32_t st = sb + 1024 + buf * STG_B;
        const uint32_t bar = sb + buf * 8;
        const size_t kB = ((size_t)chunk) << 15;             // 32KB per chunk
        MBAR_EXPECT(bar, STG_B);
        bulk_g2s(st,             cA + mbB + kB,  A_CHK, bar);
        bulk_g2s(st + A_CHK,     cB + nbB0 + kB, A_CHK, bar);
        bulk_g2s(st + 2 * A_CHK, cB + nbB1 + kB, A_CHK, bar);
    };

    if (tid == 0) { issue(0, 0); issue(1, 1); }

#pragma unroll
    for (int i = 0; i < 4; i++)
#pragma unroll
        for (int j = 0; j < 8; j++)
#pragma unroll
            for (int e = 0; e < 4; e++) acc[i][j][e] = 0.f;

    const int a_row = (lane & 15);
    const uint32_t a_cb = (uint32_t)((lane >> 4) * 16);
    const int b_row = ((lane >> 4) & 1) * 8 + (lane & 7);
    const uint32_t b_cb = (uint32_t)(((lane >> 3) & 1) * 16);
    const int wn_loc = wn & 127;                  // row within B half
    const uint32_t bHalfOff = (wn >= 128) ? A_CHK : 0;

    for (int i = 0; i < NCH; i++) {
        const int stg = i & 1;
        MBARRIER_WAIT_PARITY(sb + stg * 8, (i >> 1) & 1);

        const uint32_t st = sb + 1024 + stg * STG_B;

#pragma unroll
        for (int ks = 0; ks < 8; ks++) {
            const uint32_t sub = (uint32_t)((ks >> 2) * 16384);
            const uint32_t kb = (uint32_t)((ks & 3) * 32);
            const uint32_t aA = st + sub;
            const uint32_t bB = st + A_CHK + bHalfOff + sub;
            uint32_t af[4][4];
#pragma unroll
            for (int mi = 0; mi < 4; mi++) {
                uint32_t off = SWZ128((uint32_t)((wm + mi * 16 + a_row) * 128) + kb + a_cb);
                ldsm_x4(af[mi][0], af[mi][1], af[mi][2], af[mi][3], aA + off);
            }
#pragma unroll
            for (int hb = 0; hb < 2; hb++) {
                uint32_t bf[2][4];
#pragma unroll
                for (int g2 = 0; g2 < 2; g2++) {
                    const int ng = hb * 2 + g2;
                    uint32_t off = SWZ128((uint32_t)((wn_loc + ng * 16 + b_row) * 128) + kb + b_cb);
                    ldsm_x4(bf[g2][0], bf[g2][1], bf[g2][2], bf[g2][3], bB + off);
                }
#pragma unroll
                for (int g2 = 0; g2 < 2; g2++)
#pragma unroll
                    for (int mi = 0; mi < 4; mi++) {
                        const int nj = 2 * (hb * 2 + g2);
                        mma_fp16(acc[mi][nj],     af[mi], bf[g2][0], bf[g2][1]);
                        mma_fp16(acc[mi][nj + 1], af[mi], bf[g2][2], bf[g2][3]);
                    }
            }
        }
        __syncthreads();
        if (i + GSTAGES < NCH && tid == 0) issue(i + GSTAGES, stg);
    }
}

__device__ __forceinline__ void gemm_store_half(float acc[4][8][4], __half* Cm,
                                                int N, int m0, int n0) {
    const int tid = threadIdx.x, wid = tid >> 5, lane = tid & 31;
    const int wm = (wid & 1) * 64, wn = (wid >> 1) * 64;
    const int cr = lane >> 2;
    const int cc = (lane & 3) * 2;
#pragma unroll
    for (int mi = 0; mi < 4; mi++) {
#pragma unroll
        for (int nj = 0; nj < 8; nj++) {
            const int r = m0 + wm + mi * 16 + cr;
            const int c = n0 + wn + nj * 8 + cc;
            *(uint32_t*)&Cm[(size_t)r * N + c] = pack_half(acc[mi][nj][0], acc[mi][nj][1]);
            *(uint32_t*)&Cm[(size_t)(r + 8) * N + c] = pack_half(acc[mi][nj][2], acc[mi][nj][3]);
        }
    }
}

__device__ __forceinline__ void gemm_store_f32(float acc[4][8][4], float* Cm,
                                               int N, int m0, int n0) {
    const int tid = threadIdx.x, wid = tid >> 5, lane = tid & 31;
    const int wm = (wid & 1) * 64, wn = (wid >> 1) * 64;
    const int cr = lane >> 2;
    const int cc = (lane & 3) * 2;
#pragma unroll
    for (int mi = 0; mi < 4; mi++) {
#pragma unroll
        for (int nj = 0; nj < 8; nj++) {
            const int r = m0 + wm + mi * 16 + cr;
            const int c = n0 + wn + nj * 8 + cc;
            *(float2*)&Cm[(size_t)r * N + c] = make_float2(acc[mi][nj][0], acc[mi][nj][1]);
            *(float2*)&Cm[(size_t)(r + 8) * N + c] = make_float2(acc[mi][nj][2], acc[mi][nj][3]);
        }
    }
}

// Combined Q/K/V projection GEMM: grid.x = 20 (8 Q | 8 K | 4 V), grid.y = 32
__global__ __launch_bounds__(256, 1)
void gemm_qkv(const __half* __restrict__ x,
              const __half* __restrict__ wq, const __half* __restrict__ wk,
              const __half* __restrict__ wv,
              __half* __restrict__ qraw, __half* __restrict__ kraw,
              __half* __restrict__ vout) {
    const int nx = blockIdx.x;
    const __half* B;
    __half* Cm;
    int N, nb;
    if (nx < 8)       { B = wq; Cm = qraw; N = 2 * CDIM; nb = nx; }
    else if (nx < 16) { B = wk; Cm = kraw; N = 2 * CDIM; nb = nx - 8; }
    else              { B = wv; Cm = vout; N = CDIM;     nb = nx - 16; }

    float acc[4][8][4];
    gemm_body((const char*)x, (const char*)B, blockIdx.y, nb, acc);
    gemm_store_half(acc, Cm, N, blockIdx.y * 128, nb * 256);
}

// Output projection GEMM (fp32 out)
__global__ __launch_bounds__(256, 1)
void gemm_out(const __half* __restrict__ A, const __half* __restrict__ B,
              float* __restrict__ Cm, int N) {
    float acc[4][8][4];
    gemm_body((const char*)A, (const char*)B, blockIdx.y, blockIdx.x, acc);
    gemm_store_f32(acc, Cm, N, blockIdx.y * 128, blockIdx.x * 256);
}

// ---------------- fp32 -> single fp16, GEMM-A tiled layout ------------------
__global__ __launch_bounds__(256)
void convert_gemm(const float* __restrict__ src, __half* __restrict__ dst) {
    int i2 = blockIdx.x * 256 + threadIdx.x;
    int row = i2 >> 9, col = (i2 & 511) * 2;
    float2 v = *(const float2*)&src[(size_t)row * CDIM + col];
    size_t off = gemmA_off(row, col);
    *(uint32_t*)((char*)dst + off) = pack_half(v.x, v.y);
}

// fp16 row-major -> fp16 ATTENTION tiled layout (for V; pure relayout)
__global__ __launch_bounds__(256)
void relayout_att(const __half* __restrict__ src, __half* __restrict__ dst) {
    int i2 = blockIdx.x * 256 + threadIdx.x;
    int bt = i2 >> 9, col = (i2 & 511) * 2;
    int b = bt >> 11, t = bt & (SEQ - 1);
    int h = col >> 6, d = col & 63;
    uint32_t v = *(const uint32_t*)&src[(size_t)bt * CDIM + col];
    *(uint32_t*)((char*)dst + att_off(b, h, t, d)) = v;
}

// ---------------- merged weight transpose (all 4 weights, one launch) -------
__global__ __launch_bounds__(256)
void transpose_all(const float* __restrict__ Wq, const float* __restrict__ Wk,
                   const float* __restrict__ Wv, const float* __restrict__ Wo,
                   __half* __restrict__ Dq, __half* __restrict__ Dk,
                   __half* __restrict__ Dv, __half* __restrict__ Do_) {
    __shared__ float t[32][33];
    int bid = blockIdx.x;
    const float* W;
    __half* D;
    int N, nb, kb;
    if (bid < 2048)      { W = Wq; D = Dq; N = 2 * CDIM; nb = bid & 63; kb = bid >> 6; }
    else if (bid < 4096) { bid -= 2048; W = Wk; D = Dk; N = 2 * CDIM; nb = bid & 63; kb = bid >> 6; }
    else if (bid < 5120) { bid -= 4096; W = Wv; D = Dv; N = CDIM; nb = bid & 31; kb = bid >> 5; }
    else                 { bid -= 5120; W = Wo; D = Do_; N = CDIM; nb = bid & 31; kb = bid >> 5; }

    const int tx = threadIdx.x, ty = threadIdx.y;
    const int n0 = nb * 32, k0 = kb * 32;
#pragma unroll
    for (int i = 0; i < 32; i += 8)
        t[ty + i][tx] = W[(size_t)(k0 + ty + i) * N + n0 + tx];
    __syncthreads();
#pragma unroll
    for (int i = 0; i < 32; i += 8) {
        float v = t[tx][ty + i];
        size_t off = gemmA_off(n0 + ty + i, k0 + tx);
        *(__half*)((char*)D + off) = __float2half(v);
    }
}

// ---------------- amp/phase transform (fp16 in) -> single fp16 --------------
__device__ __forceinline__ float softplus_f(float a) {
    return (a > 20.f) ? a : log1pf(expf(a));
}

__global__ __launch_bounds__(256)
void transform_qk_fp16() {
    int i2 = blockIdx.x * 256 + threadIdx.x;
    int c2 = i2 * 2;
    int bt = c2 >> 10;
    int c  = c2 & 1023;
    int b = bt >> 11, t = bt & (SEQ - 1);
    int h = c >> 6, d = c & 63;
    size_t rbase = (size_t)bt * (2 * CDIM);
    size_t off = att_off(b, h, t, d);

    __half2 qa = *(const __half2*)&g_qraw[rbase + c];
    __half2 qp = *(const __half2*)&g_qraw[rbase + CDIM + c];
    __half2 ka = *(const __half2*)&g_kraw[rbase + c];
    __half2 kp = *(const __half2*)&g_kraw[rbase + CDIM + c];

    float qa0 = __half2float(qa.x), qa1 = __half2float(qa.y);
    float qp0 = __half2float(qp.x), qp1 = __half2float(qp.y);
    float ka0 = __half2float(ka.x), ka1 = __half2float(ka.y);
    float kp0 = __half2float(kp.x), kp1 = __half2float(kp.y);

    float qs0 = softplus_f(qa0), qs1 = softplus_f(qa1);
    float ks0 = softplus_f(ka0), ks1 = softplus_f(ka1);
    float s0, c0, s1, c1, s2, c2f, s3, c3;
    sincosf(qp0, &s0, &c0); sincosf(qp1, &s1, &c1);
    sincosf(kp0, &s2, &c2f); sincosf(kp1, &s3, &c3);

    *(uint32_t*)((char*)g_qr + off) = pack_half(qs0 * c0, qs1 * c1);
    *(uint32_t*)((char*)g_qi + off) = pack_half(qs0 * s0, qs1 * s1);
    *(uint32_t*)((char*)g_kr + off) = pack_half(ks0 * c2f, ks1 * c3);
    *(uint32_t*)((char*)g_ki + off) = pack_half(ks0 * s2, ks1 * s3);
}

__global__ void gate_init(const float* __restrict__ theta) {
    int i = blockIdx.x * 256 + threadIdx.x;
    int h = i >> 11, s = i & (SEQ - 1);
    float th = theta[h] * (1.0f / GAMMA_F);
    float sn, cs;
    sincosf(th * (float)s, &sn, &cs);
    g_gate[i] = make_float2(cs, sn);
}

// ---------------- fully fp16 flash attention with moiré gate ----------------
#define AQT 128
#define AST 64
#define AQ_TILE 16384
#define AKV_TILE 8192
#define AKV_BUF (3 * AKV_TILE)              // 24576
#define AKV_STAGES 4
#define ATT_SMEM (1024 + 2 * AQ_TILE + AKV_STAGES * AKV_BUF)  // 132096

__global__ __launch_bounds__(256)
void attn_mma() {
    extern __shared__ char smem[];
    const uint32_t sb = smem_u32(smem);
    const uint32_t sQ  = sb + 1024;
    const uint32_t sKV = sQ + 2 * AQ_TILE;

    const int tid = threadIdx.x, w = tid >> 5, lane = tid & 31;
    const int q0 = (int)(gridDim.x - 1 - blockIdx.x) * AQT;
    const int h = blockIdx.y, b = blockIdx.z;
    const int nS = q0 / AST + 2;

    const size_t bhB = ((size_t)((b * HEADS + h) * 32)) << 13;

    if (tid == 0) {
        MBARRIER_INIT(sb, 1);
#pragma unroll
        for (int s = 0; s < AKV_STAGES; s++) MBARRIER_INIT(sb + 8 + s * 8, 1);
    }
    __syncthreads();

    auto issue_kv = [&](int chunk, int buf) {
        const uint32_t st = sKV + buf * AKV_BUF;
        const uint32_t bar = sb + 8 + buf * 8;
        const size_t src = bhB + (((size_t)chunk) << 13);
        MBAR_EXPECT(bar, AKV_BUF);
        bulk_g2s(st,                (const char*)g_kr + src, AKV_TILE, bar);
        bulk_g2s(st + AKV_TILE,     (const char*)g_ki + src, AKV_TILE, bar);
        bulk_g2s(st + 2 * AKV_TILE, (const char*)g_vv + src, AKV_TILE, bar);
    };

    if (tid == 0) {
        const size_t qsrc = bhB + (((size_t)(q0 >> 6)) << 13);
        MBAR_EXPECT(sb, 2 * AQ_TILE);
        bulk_g2s(sQ,           (const char*)g_qr + qsrc, AQ_TILE, sb);
        bulk_g2s(sQ + AQ_TILE, (const char*)g_qi + qsrc, AQ_TILE, sb);
#pragma unroll
        for (int c = 0; c < AKV_STAGES; c++)
            if (c < nS) issue_kv(c, c);
    }

    const int a_row = lane & 15;
    const uint32_t a_cb = (uint32_t)((lane >> 4) * 16);
    const int b_row = ((lane >> 4) & 1) * 8 + (lane & 7);
    const uint32_t b_cb = (uint32_t)(((lane >> 3) & 1) * 16);

    const int t0g = q0 + w * 16 + (lane >> 2);
    const int t1g = t0g + 8;
    const float2 gt0 = g_gate[h * SEQ + t0g];
    const float2 gt1 = g_gate[h * SEQ + t1g];

    float m0 = -INFINITY, m1 = -INFINITY, l0 = 0.f, l1 = 0.f;
    float oacc[8][4];
#pragma unroll
    for (int f = 0; f < 8; f++)
#pragma unroll
        for (int e = 0; e < 4; e++) oacc[f][e] = 0.f;

    MBARRIER_WAIT_PARITY(sb, 0);

    for (int i = 0; i < nS; i++) {
        const int stg = i % AKV_STAGES;
        MBARRIER_WAIT_PARITY(sb + 8 + stg * 8, (i / AKV_STAGES) & 1);

        const int s0 = i * AST;
        const uint32_t kb0 = sKV + stg * AKV_BUF;
        const uint32_t kR = kb0, kI = kb0 + AKV_TILE, vT = kb0 + 2 * AKV_TILE;

        float sacc[8][4];
#pragma unroll
        for (int f = 0; f < 8; f++)
#pragma unroll
            for (int e = 0; e < 4; e++) sacc[f][e] = 0.f;

#pragma unroll
        for (int jd = 0; jd < 4; jd++) {
            const uint32_t kb = (uint32_t)(jd * 32);
            const uint32_t offA = SWZ128((uint32_t)((w * 16 + a_row) * 128) + kb + a_cb);
            uint32_t aqr[4], aqi[4];
            ldsm_x4(aqr[0], aqr[1], aqr[2], aqr[3], sQ + offA);
            ldsm_x4(aqi[0], aqi[1], aqi[2], aqi[3], sQ + AQ_TILE + offA);
#pragma unroll
            for (int gp = 0; gp < 2; gp++) {
                uint32_t rf[2][4], imf[2][4];
#pragma unroll
                for (int g2 = 0; g2 < 2; g2++) {
                    const int g = gp * 2 + g2;
                    const uint32_t offB = SWZ128((uint32_t)((g * 16 + b_row) * 128) + kb + b_cb);
                    ldsm_x4(rf[g2][0], rf[g2][1], rf[g2][2], rf[g2][3], kR + offB);
                    ldsm_x4(imf[g2][0], imf[g2][1], imf[g2][2], imf[g2][3], kI + offB);
                }
#pragma unroll
                for (int g2 = 0; g2 < 2; g2++) {
                    const int s2 = 2 * (gp * 2 + g2);
                    mma_fp16(sacc[s2],     aqr, rf[g2][0], rf[g2][1]);
                    mma_fp16(sacc[s2 + 1], aqr, rf[g2][2], rf[g2][3]);
                }
#pragma unroll
                for (int g2 = 0; g2 < 2; g2++) {
                    const int s2 = 2 * (gp * 2 + g2);
                    mma_fp16(sacc[s2],     aqi, imf[g2][0], imf[g2][1]);
                    mma_fp16(sacc[s2 + 1], aqi, imf[g2][2], imf[g2][3]);
                }
            }
        }

        float pm0 = -INFINITY, pm1 = -INFINITY;
#pragma unroll
        for (int f = 0; f < 8; f++) {
            const int sb2 = s0 + f * 8 + (lane & 3) * 2;
            const float2 gs0 = g_gate[h * SEQ + sb2];
            const float2 gs1 = g_gate[h * SEQ + sb2 + 1];
            float v00 = sacc[f][0] * SCALE_F * (gs0.x * gt0.x + gs0.y * gt0.y);
            float v01 = sacc[f][1] * SCALE_F * (gs1.x * gt0.x + gs1.y * gt0.y);
            float v10 = sacc[f][2] * SCALE_F * (gs0.x * gt1.x + gs0.y * gt1.y);
            float v11 = sacc[f][3] * SCALE_F * (gs1.x * gt1.x + gs1.y * gt1.y);
            if (sb2 > t0g)     v00 = -INFINITY;
            if (sb2 + 1 > t0g) v01 = -INFINITY;
            if (sb2 > t1g)     v10 = -INFINITY;
            if (sb2 + 1 > t1g) v11 = -INFINITY;
            sacc[f][0] = v00; sacc[f][1] = v01; sacc[f][2] = v10; sacc[f][3] = v11;
            pm0 = fmaxf(pm0, fmaxf(v00, v01));
            pm1 = fmaxf(pm1, fmaxf(v10, v11));
        }
        pm0 = fmaxf(pm0, __shfl_xor_sync(0xffffffffu, pm0, 1));
        pm0 = fmaxf(pm0, __shfl_xor_sync(0xffffffffu, pm0, 2));
        pm1 = fmaxf(pm1, __shfl_xor_sync(0xffffffffu, pm1, 1));
        pm1 = fmaxf(pm1, __shfl_xor_sync(0xffffffffu, pm1, 2));

        const float mn0 = fmaxf(m0, pm0), mn1 = fmaxf(m1, pm1);
        const float cr0 = __expf(m0 - mn0), cr1 = __expf(m1 - mn1);
        float rs0 = 0.f, rs1 = 0.f;
#pragma unroll
        for (int f = 0; f < 8; f++) {
            sacc[f][0] = __expf(sacc[f][0] - mn0);
            sacc[f][1] = __expf(sacc[f][1] - mn0);
            sacc[f][2] = __expf(sacc[f][2] - mn1);
            sacc[f][3] = __expf(sacc[f][3] - mn1);
            rs0 += sacc[f][0] + sacc[f][1];
            rs1 += sacc[f][2] + sacc[f][3];
        }
        rs0 += __shfl_xor_sync(0xffffffffu, rs0, 1);
        rs0 += __shfl_xor_sync(0xffffffffu, rs0, 2);
        rs1 += __shfl_xor_sync(0xffffffffu, rs1, 1);
        rs1 += __shfl_xor_sync(0xffffffffu, rs1, 2);
        l0 = l0 * cr0 + rs0; m0 = mn0;
        l1 = l1 * cr1 + rs1; m1 = mn1;
#pragma unroll
        for (int f = 0; f < 8; f++) {
            oacc[f][0] *= cr0; oacc[f][1] *= cr0;
            oacc[f][2] *= cr1; oacc[f][3] *= cr1;
        }

#pragma unroll
        for (int j = 0; j < 4; j++) {
            uint32_t ph[4] = {
                pack_half(sacc[2 * j][0],     sacc[2 * j][1]),
                pack_half(sacc[2 * j][2],     sacc[2 * j][3]),
                pack_half(sacc[2 * j + 1][0], sacc[2 * j + 1][1]),
                pack_half(sacc[2 * j + 1][2], sacc[2 * j + 1][3])};
#pragma unroll
            for (int dgp = 0; dgp < 2; dgp++) {
                uint32_t vf[2][4];
#pragma unroll
                for (int d2 = 0; d2 < 2; d2++) {
                    const int dg = dgp * 2 + d2;
                    const uint32_t offV = SWZ128((uint32_t)((16 * j + a_row) * 128) +
                                                 (uint32_t)(dg * 32) + a_cb);
                    ldsm_x4_t(vf[d2][0], vf[d2][1], vf[d2][2], vf[d2][3], vT + offV);
                }
#pragma unroll
                for (int d2 = 0; d2 < 2; d2++) {
                    const int o2 = 2 * (dgp * 2 + d2);
                    mma_fp16(oacc[o2],     ph, vf[d2][0], vf[d2][1]);
                    mma_fp16(oacc[o2 + 1], ph, vf[d2][2], vf[d2][3]);
                }
            }
        }
        __syncthreads();
        if (i + AKV_STAGES < nS && tid == 0) issue_kv(i + AKV_STAGES, stg);
    }

    // epilogue: normalize, write single fp16 in GEMM-A tiled layout
    const float iv0 = 1.0f / l0, iv1 = 1.0f / l1;
#pragma unroll
    for (int f = 0; f < 8; f++) {
        const int d = f * 8 + (lane & 3) * 2;
        size_t off0 = gemmA_off(b * SEQ + t0g, h * 64 + d);
        size_t off1 = gemmA_off(b * SEQ + t1g, h * 64 + d);
        *(uint32_t*)((char*)g_a + off0) = pack_half(oacc[f][0] * iv0, oacc[f][1] * iv0);
        *(uint32_t*)((char*)g_a + off1) = pack_half(oacc[f][2] * iv1, oacc[f][3] * iv1);
    }
}

// ---------------- launch ---------------------------------------------------
extern "C" void kernel_launch(void* const* d_in, const int* in_sizes, int n_in,
                              void* d_out, int out_size) {
    const float* x     = (const float*)d_in[0];
    const float* Wq    = (const float*)d_in[1];
    const float* Wk    = (const float*)d_in[2];
    const float* Wv    = (const float*)d_in[3];
    const float* Wo    = (const float*)d_in[4];
    const float* theta = (const float*)d_in[5];
    float* out = (float*)d_out;

    __half *qraw, *kraw, *vraw;
    __half *xg, *ag, *vv, *wq, *wk, *wv, *wo;
    cudaGetSymbolAddress((void**)&qraw, g_qraw);
    cudaGetSymbolAddress((void**)&kraw, g_kraw);
    cudaGetSymbolAddress((void**)&vraw, g_vraw);
    cudaGetSymbolAddress((void**)&xg,  g_x);
    cudaGetSymbolAddress((void**)&ag,  g_a);
    cudaGetSymbolAddress((void**)&vv,  g_vv);
    cudaGetSymbolAddress((void**)&wq,  g_wq);
    cudaGetSymbolAddress((void**)&wk,  g_wk);
    cudaGetSymbolAddress((void**)&wv,  g_wv);
    cudaGetSymbolAddress((void**)&wo,  g_wo);

    cudaFuncSetAttribute(gemm_qkv,
                         cudaFuncAttributeMaxDynamicSharedMemorySize, GEMM_SMEM);
    cudaFuncSetAttribute(gemm_out,
                         cudaFuncAttributeMaxDynamicSharedMemorySize, GEMM_SMEM);
    cudaFuncSetAttribute(attn_mma,
                         cudaFuncAttributeMaxDynamicSharedMemorySize, ATT_SMEM);

    convert_gemm<<<MROWS * CDIM / 2 / 256, 256>>>(x, xg);
    gate_init<<<HEADS * SEQ / 256, 256>>>(theta);
    transpose_all<<<6144, dim3(32, 8)>>>(Wq, Wk, Wv, Wo, wq, wk, wv, wo);

    gemm_qkv<<<dim3(20, MROWS / 128), 256, GEMM_SMEM>>>(
        xg, wq, wk, wv, qraw, kraw, vraw);

    transform_qk_fp16<<<MROWS * CDIM / 2 / 256, 256>>>();
    relayout_att<<<MROWS * CDIM / 2 / 256, 256>>>(vraw, vv);

    attn_mma<<<dim3(SEQ / AQT, HEADS, BATCH), 256, ATT_SMEM>>>();

    gemm_out<<<dim3(CDIM / 256, MROWS / 128), 256, GEMM_SMEM>>>(ag, wo, out, CDIM);
}

// round 16
// speedup vs baseline: 2.1290x; 1.0256x over previous
#include <cuda_runtime.h>
#include <cuda_bf16.h>
#include <cuda_fp16.h>
#include <cstdint>
#include <math.h>

// Problem constants
#define BATCH   2
#define SEQ     2048
#define CDIM    1024
#define HEADS   16
#define HDIM    64
#define GAMMA_F 8.0f
#define SCALE_F 0.125f
#define MROWS   (BATCH*SEQ)          // 4096
#define KDIM    1024

// ---------------- scratch (device globals; no allocation allowed) ----------
__device__ __half g_qraw[MROWS * 2 * CDIM];   // fp16 raw projections
__device__ __half g_kraw[MROWS * 2 * CDIM];

// fp16 GEMM operands (pre-swizzled tile-blocked layouts) -- ALL single fp16
__device__ __half g_x  [MROWS * CDIM];
__device__ __half g_a  [MROWS * CDIM];
__device__ __half g_wq [2 * CDIM * CDIM];
__device__ __half g_wk [2 * CDIM * CDIM];
__device__ __half g_wv [CDIM * CDIM];
__device__ __half g_wo [CDIM * CDIM];

// attention operands: ALL single fp16
__device__ __half g_qr [MROWS * CDIM];
__device__ __half g_qi [MROWS * CDIM];
__device__ __half g_kr [MROWS * CDIM];
__device__ __half g_ki [MROWS * CDIM];
__device__ __half g_vv [MROWS * CDIM];
__device__ float2 g_gate[HEADS * SEQ];

// ---------------- helpers ---------------------------------------------------
__device__ __forceinline__ uint32_t smem_u32(const void* p) {
    uint32_t a;
    asm("{ .reg .u64 t; cvta.to.shared.u64 t, %1; cvt.u32.u64 %0, t; }"
        : "=r"(a) : "l"(p));
    return a;
}
#define SWZ128(o) ((o) ^ (((o) >> 3) & 0x70))

__device__ __forceinline__ size_t gemmA_off(int row, int col) {
    return ((size_t)((row >> 7) * 16 + (col >> 6)) << 14) +
           SWZ128((uint32_t)((row & 127) * 128 + (col & 63) * 2));
}
__device__ __forceinline__ size_t att_off(int b, int h, int t, int d) {
    return ((size_t)((b * HEADS + h) * 32 + (t >> 6)) << 13) +
           SWZ128((uint32_t)((t & 63) * 128 + d * 2));
}

#define MBARRIER_INIT(mbar, count) \
    asm volatile("mbarrier.init.shared.b64 [%0], %1;" :: "r"((uint32_t)(mbar)), "r"((uint32_t)(count)) : "memory")
#define MBAR_EXPECT(mbar, bytes) \
    asm volatile("mbarrier.arrive.expect_tx.shared.b64 _, [%0], %1;" :: "r"((uint32_t)(mbar)), "r"((uint32_t)(bytes)) : "memory")

#define MBARRIER_WAIT_PARITY(mbar, parity) do { \
    uint32_t _m = (uint32_t)(mbar); uint32_t _p = (uint32_t)(parity); uint32_t _d; \
    asm volatile("{\n\t.reg .pred p;\n\t" \
        "mbarrier.try_wait.parity.acquire.cta.shared::cta.b64 p, [%1], %2;\n\t" \
        "selp.b32 %0, 1, 0, p;\n\t}" : "=r"(_d) : "r"(_m), "r"(_p) : "memory"); \
    if (!_d) { \
        asm volatile("{\n\t.reg .pred P1;\n\t" \
            "WL_%=:\n\t" \
            "mbarrier.try_wait.parity.acquire.cta.shared::cta.b64 P1, [%0], %1, 0x989680;\n\t" \
            "@P1 bra.uni WD_%=;\n\tbra.uni WL_%=;\n\tWD_%=:\n\t}" \
            :: "r"(_m), "r"(_p) : "memory"); \
    } } while (0)

__device__ __forceinline__ void bulk_g2s(uint32_t dst, const void* src,
                                         uint32_t bytes, uint32_t mbar) {
    asm volatile(
        "cp.async.bulk.shared::cluster.global.mbarrier::complete_tx::bytes [%0], [%1], %2, [%3];"
        :: "r"(dst), "l"(src), "r"(bytes), "r"(mbar) : "memory");
}

__device__ __forceinline__ void ldsm_x4(uint32_t& r0, uint32_t& r1,
                                        uint32_t& r2, uint32_t& r3, uint32_t addr) {
    asm volatile("ldmatrix.sync.aligned.m8n8.x4.shared.b16 {%0,%1,%2,%3}, [%4];"
                 : "=r"(r0), "=r"(r1), "=r"(r2), "=r"(r3) : "r"(addr));
}
__device__ __forceinline__ void ldsm_x4_t(uint32_t& r0, uint32_t& r1,
                                          uint32_t& r2, uint32_t& r3, uint32_t addr) {
    asm volatile("ldmatrix.sync.aligned.m8n8.x4.trans.shared.b16 {%0,%1,%2,%3}, [%4];"
                 : "=r"(r0), "=r"(r1), "=r"(r2), "=r"(r3) : "r"(addr));
}

__device__ __forceinline__ void mma_fp16(float* c, const uint32_t* a,
                                         uint32_t b0, uint32_t b1) {
    asm volatile(
        "mma.sync.aligned.m16n8k16.row.col.f32.f16.f16.f32 "
        "{%0,%1,%2,%3}, {%4,%5,%6,%7}, {%8,%9}, {%0,%1,%2,%3};"
        : "+f"(c[0]), "+f"(c[1]), "+f"(c[2]), "+f"(c[3])
        : "r"(a[0]), "r"(a[1]), "r"(a[2]), "r"(a[3]), "r"(b0), "r"(b1));
}

__device__ __forceinline__ uint32_t pack_half(float a, float b) {
    __half2 t = __floats2half2_rn(a, b);
    return *reinterpret_cast<uint32_t*>(&t);
}

// ---------------- single-fp16 GEMM: C = A[M,K] * B[N,K]^T -------------------
// Block 128x256, 8 warps 64x64, K-chunk 128, 2-stage bulk pipeline, 1 MMA pass.
#define BK       128
#define NCH      (KDIM / BK)             // 8
#define A_CHK    32768
#define STG_B    (3 * A_CHK)             // 98304
#define GSTAGES  2
#define GEMM_SMEM (1024 + GSTAGES * STG_B)  // 197632

__device__ __forceinline__ void gemm_body(
    const char* cA, const char* cB, int mb, int nb, float acc[4][8][4]) {
    extern __shared__ char smem[];
    const uint32_t sb = smem_u32(smem);
    const int tid = threadIdx.x, wid = tid >> 5, lane = tid & 31;
    const int wm = (wid & 1) * 64;
    const int wn = (wid >> 1) * 64;

    const size_t mbB  = ((size_t)mb * 16) << 14;
    const size_t nbB0 = ((size_t)(nb * 2) * 16) << 14;
    const size_t nbB1 = ((size_t)(nb * 2 + 1) * 16) << 14;

    if (tid == 0) { MBARRIER_INIT(sb, 1); MBARRIER_INIT(sb + 8, 1); }
    __syncthreads();

    auto issue = [&](int chunk, int buf) {
        const uint32_t st = sb + 1024 + buf * STG_B;
        const uint32_t bar = sb + buf * 8;
        const size_t kB = ((size_t)chunk) << 15;
        MBAR_EXPECT(bar, STG_B);
        bulk_g2s(st,             cA + mbB + kB,  A_CHK, bar);
        bulk_g2s(st + A_CHK,     cB + nbB0 + kB, A_CHK, bar);
        bulk_g2s(st + 2 * A_CHK, cB + nbB1 + kB, A_CHK, bar);
    };

    if (tid == 0) { issue(0, 0); issue(1, 1); }

#pragma unroll
    for (int i = 0; i < 4; i++)
#pragma unroll
        for (int j = 0; j < 8; j++)
#pragma unroll
            for (int e = 0; e < 4; e++) acc[i][j][e] = 0.f;

    const int a_row = (lane & 15);
    const uint32_t a_cb = (uint32_t)((lane >> 4) * 16);
    const int b_row = ((lane >> 4) & 1) * 8 + (lane & 7);
    const uint32_t b_cb = (uint32_t)(((lane >> 3) & 1) * 16);
    const int wn_loc = wn & 127;
    const uint32_t bHalfOff = (wn >= 128) ? A_CHK : 0;

    for (int i = 0; i < NCH; i++) {
        const int stg = i & 1;
        MBARRIER_WAIT_PARITY(sb + stg * 8, (i >> 1) & 1);

        const uint32_t st = sb + 1024 + stg * STG_B;

#pragma unroll
        for (int ks = 0; ks < 8; ks++) {
            const uint32_t sub = (uint32_t)((ks >> 2) * 16384);
            const uint32_t kb = (uint32_t)((ks & 3) * 32);
            const uint32_t aA = st + sub;
            const uint32_t bB = st + A_CHK + bHalfOff + sub;
            uint32_t af[4][4];
#pragma unroll
            for (int mi = 0; mi < 4; mi++) {
                uint32_t off = SWZ128((uint32_t)((wm + mi * 16 + a_row) * 128) + kb + a_cb);
                ldsm_x4(af[mi][0], af[mi][1], af[mi][2], af[mi][3], aA + off);
            }
#pragma unroll
            for (int hb = 0; hb < 2; hb++) {
                uint32_t bf[2][4];
#pragma unroll
                for (int g2 = 0; g2 < 2; g2++) {
                    const int ng = hb * 2 + g2;
                    uint32_t off = SWZ128((uint32_t)((wn_loc + ng * 16 + b_row) * 128) + kb + b_cb);
                    ldsm_x4(bf[g2][0], bf[g2][1], bf[g2][2], bf[g2][3], bB + off);
                }
#pragma unroll
                for (int g2 = 0; g2 < 2; g2++)
#pragma unroll
                    for (int mi = 0; mi < 4; mi++) {
                        const int nj = 2 * (hb * 2 + g2);
                        mma_fp16(acc[mi][nj],     af[mi], bf[g2][0], bf[g2][1]);
                        mma_fp16(acc[mi][nj + 1], af[mi], bf[g2][2], bf[g2][3]);
                    }
            }
        }
        __syncthreads();
        if (i + GSTAGES < NCH && tid == 0) issue(i + GSTAGES, stg);
    }
}

__device__ __forceinline__ void gemm_store_half(float acc[4][8][4], __half* Cm,
                                                int N, int m0, int n0) {
    const int tid = threadIdx.x, wid = tid >> 5, lane = tid & 31;
    const int wm = (wid & 1) * 64, wn = (wid >> 1) * 64;
    const int cr = lane >> 2;
    const int cc = (lane & 3) * 2;
#pragma unroll
    for (int mi = 0; mi < 4; mi++) {
#pragma unroll
        for (int nj = 0; nj < 8; nj++) {
            const int r = m0 + wm + mi * 16 + cr;
            const int c = n0 + wn + nj * 8 + cc;
            *(uint32_t*)&Cm[(size_t)r * N + c] = pack_half(acc[mi][nj][0], acc[mi][nj][1]);
            *(uint32_t*)&Cm[(size_t)(r + 8) * N + c] = pack_half(acc[mi][nj][2], acc[mi][nj][3]);
        }
    }
}

// store directly into ATTENTION tiled layout (for V)
__device__ __forceinline__ void gemm_store_att(float acc[4][8][4], __half* Cm,
                                               int m0, int n0) {
    const int tid = threadIdx.x, wid = tid >> 5, lane = tid & 31;
    const int wm = (wid & 1) * 64, wn = (wid >> 1) * 64;
    const int cr = lane >> 2;
    const int cc = (lane & 3) * 2;
#pragma unroll
    for (int mi = 0; mi < 4; mi++) {
#pragma unroll
        for (int nj = 0; nj < 8; nj++) {
            const int c = n0 + wn + nj * 8 + cc;   // even; c,c+1 same head
            const int h = c >> 6, d = c & 63;
#pragma unroll
            for (int rr = 0; rr < 2; rr++) {
                const int r = m0 + wm + mi * 16 + cr + rr * 8;
                const int b = r >> 11, t = r & (SEQ - 1);
                *(uint32_t*)((char*)Cm + att_off(b, h, t, d)) =
                    pack_half(acc[mi][nj][2 * rr], acc[mi][nj][2 * rr + 1]);
            }
        }
    }
}

__device__ __forceinline__ void gemm_store_f32(float acc[4][8][4], float* Cm,
                                               int N, int m0, int n0) {
    const int tid = threadIdx.x, wid = tid >> 5, lane = tid & 31;
    const int wm = (wid & 1) * 64, wn = (wid >> 1) * 64;
    const int cr = lane >> 2;
    const int cc = (lane & 3) * 2;
#pragma unroll
    for (int mi = 0; mi < 4; mi++) {
#pragma unroll
        for (int nj = 0; nj < 8; nj++) {
            const int r = m0 + wm + mi * 16 + cr;
            const int c = n0 + wn + nj * 8 + cc;
            *(float2*)&Cm[(size_t)r * N + c] = make_float2(acc[mi][nj][0], acc[mi][nj][1]);
            *(float2*)&Cm[(size_t)(r + 8) * N + c] = make_float2(acc[mi][nj][2], acc[mi][nj][3]);
        }
    }
}

// Combined Q/K/V projection GEMM: grid.x = 20 (8 Q | 8 K | 4 V), grid.y = 32
__global__ __launch_bounds__(256, 1)
void gemm_qkv(const __half* __restrict__ x,
              const __half* __restrict__ wq, const __half* __restrict__ wk,
              const __half* __restrict__ wv,
              __half* __restrict__ qraw, __half* __restrict__ kraw,
              __half* __restrict__ vatt) {
    const int nx = blockIdx.x;
    float acc[4][8][4];
    if (nx < 8) {
        gemm_body((const char*)x, (const char*)wq, blockIdx.y, nx, acc);
        gemm_store_half(acc, qraw, 2 * CDIM, blockIdx.y * 128, nx * 256);
    } else if (nx < 16) {
        gemm_body((const char*)x, (const char*)wk, blockIdx.y, nx - 8, acc);
        gemm_store_half(acc, kraw, 2 * CDIM, blockIdx.y * 128, (nx - 8) * 256);
    } else {
        gemm_body((const char*)x, (const char*)wv, blockIdx.y, nx - 16, acc);
        gemm_store_att(acc, vatt, blockIdx.y * 128, (nx - 16) * 256);
    }
}

// Output projection GEMM (fp32 out)
__global__ __launch_bounds__(256, 1)
void gemm_out(const __half* __restrict__ A, const __half* __restrict__ B,
              float* __restrict__ Cm, int N) {
    float acc[4][8][4];
    gemm_body((const char*)A, (const char*)B, blockIdx.y, blockIdx.x, acc);
    gemm_store_f32(acc, Cm, N, blockIdx.y * 128, blockIdx.x * 256);
}

// ---------------- merged prep: weight transposes + x convert + gate ---------
// grid: [0,6144) transposes, [6144,14336) x convert, [14336,14464) gate
__global__ __launch_bounds__(256)
void prep_all(const float* __restrict__ x,
              const float* __restrict__ Wq, const float* __restrict__ Wk,
              const float* __restrict__ Wv, const float* __restrict__ Wo,
              const float* __restrict__ theta,
              __half* __restrict__ Dx,
              __half* __restrict__ Dq, __half* __restrict__ Dk,
              __half* __restrict__ Dv, __half* __restrict__ Do_) {
    int bid = blockIdx.x;
    const int tid1 = threadIdx.y * 32 + threadIdx.x;

    if (bid < 6144) {
        __shared__ float t[32][33];
        const float* W;
        __half* D;
        int N, nb, kb;
        if (bid < 2048)      { W = Wq; D = Dq; N = 2 * CDIM; nb = bid & 63; kb = bid >> 6; }
        else if (bid < 4096) { bid -= 2048; W = Wk; D = Dk; N = 2 * CDIM; nb = bid & 63; kb = bid >> 6; }
        else if (bid < 5120) { bid -= 4096; W = Wv; D = Dv; N = CDIM; nb = bid & 31; kb = bid >> 5; }
        else                 { bid -= 5120; W = Wo; D = Do_; N = CDIM; nb = bid & 31; kb = bid >> 5; }

        const int tx = threadIdx.x, ty = threadIdx.y;
        const int n0 = nb * 32, k0 = kb * 32;
#pragma unroll
        for (int i = 0; i < 32; i += 8)
            t[ty + i][tx] = W[(size_t)(k0 + ty + i) * N + n0 + tx];
        __syncthreads();
#pragma unroll
        for (int i = 0; i < 32; i += 8) {
            float v = t[tx][ty + i];
            size_t off = gemmA_off(n0 + ty + i, k0 + tx);
            *(__half*)((char*)D + off) = __float2half(v);
        }
    } else if (bid < 14336) {
        int i2 = (bid - 6144) * 256 + tid1;
        int row = i2 >> 9, col = (i2 & 511) * 2;
        float2 v = *(const float2*)&x[(size_t)row * CDIM + col];
        size_t off = gemmA_off(row, col);
        *(uint32_t*)((char*)Dx + off) = pack_half(v.x, v.y);
    } else {
        int i = (bid - 14336) * 256 + tid1;
        int h = i >> 11, s = i & (SEQ - 1);
        float th = theta[h] * (1.0f / GAMMA_F);
        float sn, cs;
        sincosf(th * (float)s, &sn, &cs);
        g_gate[i] = make_float2(cs, sn);
    }
}

// ---------------- amp/phase transform (fp16 in) -> single fp16 --------------
__device__ __forceinline__ float softplus_f(float a) {
    return (a > 20.f) ? a : log1pf(expf(a));
}

__global__ __launch_bounds__(256)
void transform_qk_fp16() {
    int i2 = blockIdx.x * 256 + threadIdx.x;
    int c2 = i2 * 2;
    int bt = c2 >> 10;
    int c  = c2 & 1023;
    int b = bt >> 11, t = bt & (SEQ - 1);
    int h = c >> 6, d = c & 63;
    size_t rbase = (size_t)bt * (2 * CDIM);
    size_t off = att_off(b, h, t, d);

    __half2 qa = *(const __half2*)&g_qraw[rbase + c];
    __half2 qp = *(const __half2*)&g_qraw[rbase + CDIM + c];
    __half2 ka = *(const __half2*)&g_kraw[rbase + c];
    __half2 kp = *(const __half2*)&g_kraw[rbase + CDIM + c];

    float qa0 = __half2float(qa.x), qa1 = __half2float(qa.y);
    float qp0 = __half2float(qp.x), qp1 = __half2float(qp.y);
    float ka0 = __half2float(ka.x), ka1 = __half2float(ka.y);
    float kp0 = __half2float(kp.x), kp1 = __half2float(kp.y);

    float qs0 = softplus_f(qa0), qs1 = softplus_f(qa1);
    float ks0 = softplus_f(ka0), ks1 = softplus_f(ka1);
    float s0, c0, s1, c1, s2, c2f, s3, c3;
    sincosf(qp0, &s0, &c0); sincosf(qp1, &s1, &c1);
    sincosf(kp0, &s2, &c2f); sincosf(kp1, &s3, &c3);

    *(uint32_t*)((char*)g_qr + off) = pack_half(qs0 * c0, qs1 * c1);
    *(uint32_t*)((char*)g_qi + off) = pack_half(qs0 * s0, qs1 * s1);
    *(uint32_t*)((char*)g_kr + off) = pack_half(ks0 * c2f, ks1 * c3);
    *(uint32_t*)((char*)g_ki + off) = pack_half(ks0 * s2, ks1 * s3);
}

// ---------------- fully fp16 flash attention with moiré gate ----------------
#define AQT 128
#define AST 64
#define AQ_TILE 16384
#define AKV_TILE 8192
#define AKV_BUF (3 * AKV_TILE)              // 24576
#define AKV_STAGES 4
#define ATT_SMEM (1024 + 2 * AQ_TILE + AKV_STAGES * AKV_BUF)  // 132096

__global__ __launch_bounds__(256)
void attn_mma() {
    extern __shared__ char smem[];
    const uint32_t sb = smem_u32(smem);
    const uint32_t sQ  = sb + 1024;
    const uint32_t sKV = sQ + 2 * AQ_TILE;

    const int tid = threadIdx.x, w = tid >> 5, lane = tid & 31;
    const int q0 = (int)(gridDim.x - 1 - blockIdx.x) * AQT;
    const int h = blockIdx.y, b = blockIdx.z;
    const int nS = q0 / AST + 2;

    const size_t bhB = ((size_t)((b * HEADS + h) * 32)) << 13;

    if (tid == 0) {
        MBARRIER_INIT(sb, 1);
#pragma unroll
        for (int s = 0; s < AKV_STAGES; s++) MBARRIER_INIT(sb + 8 + s * 8, 1);
    }
    __syncthreads();

    auto issue_kv = [&](int chunk, int buf) {
        const uint32_t st = sKV + buf * AKV_BUF;
        const uint32_t bar = sb + 8 + buf * 8;
        const size_t src = bhB + (((size_t)chunk) << 13);
        MBAR_EXPECT(bar, AKV_BUF);
        bulk_g2s(st,                (const char*)g_kr + src, AKV_TILE, bar);
        bulk_g2s(st + AKV_TILE,     (const char*)g_ki + src, AKV_TILE, bar);
        bulk_g2s(st + 2 * AKV_TILE, (const char*)g_vv + src, AKV_TILE, bar);
    };

    if (tid == 0) {
        const size_t qsrc = bhB + (((size_t)(q0 >> 6)) << 13);
        MBAR_EXPECT(sb, 2 * AQ_TILE);
        bulk_g2s(sQ,           (const char*)g_qr + qsrc, AQ_TILE, sb);
        bulk_g2s(sQ + AQ_TILE, (const char*)g_qi + qsrc, AQ_TILE, sb);
#pragma unroll
        for (int c = 0; c < AKV_STAGES; c++)
            if (c < nS) issue_kv(c, c);
    }

    const int a_row = lane & 15;
    const uint32_t a_cb = (uint32_t)((lane >> 4) * 16);
    const int b_row = ((lane >> 4) & 1) * 8 + (lane & 7);
    const uint32_t b_cb = (uint32_t)(((lane >> 3) & 1) * 16);

    const int t0g = q0 + w * 16 + (lane >> 2);
    const int t1g = t0g + 8;
    const float2 gt0 = g_gate[h * SEQ + t0g];
    const float2 gt1 = g_gate[h * SEQ + t1g];

    float m0 = -INFINITY, m1 = -INFINITY, l0 = 0.f, l1 = 0.f;
    float oacc[8][4];
#pragma unroll
    for (int f = 0; f < 8; f++)
#pragma unroll
        for (int e = 0; e < 4; e++) oacc[f][e] = 0.f;

    MBARRIER_WAIT_PARITY(sb, 0);

    for (int i = 0; i < nS; i++) {
        const int stg = i % AKV_STAGES;
        MBARRIER_WAIT_PARITY(sb + 8 + stg * 8, (i / AKV_STAGES) & 1);

        const int s0 = i * AST;
        const uint32_t kb0 = sKV + stg * AKV_BUF;
        const uint32_t kR = kb0, kI = kb0 + AKV_TILE, vT = kb0 + 2 * AKV_TILE;

        float sacc[8][4];
#pragma unroll
        for (int f = 0; f < 8; f++)
#pragma unroll
            for (int e = 0; e < 4; e++) sacc[f][e] = 0.f;

#pragma unroll
        for (int jd = 0; jd < 4; jd++) {
            const uint32_t kb = (uint32_t)(jd * 32);
            const uint32_t offA = SWZ128((uint32_t)((w * 16 + a_row) * 128) + kb + a_cb);
            uint32_t aqr[4], aqi[4];
            ldsm_x4(aqr[0], aqr[1], aqr[2], aqr[3], sQ + offA);
            ldsm_x4(aqi[0], aqi[1], aqi[2], aqi[3], sQ + AQ_TILE + offA);
#pragma unroll
            for (int gp = 0; gp < 2; gp++) {
                uint32_t rf[2][4], imf[2][4];
#pragma unroll
                for (int g2 = 0; g2 < 2; g2++) {
                    const int g = gp * 2 + g2;
                    const uint32_t offB = SWZ128((uint32_t)((g * 16 + b_row) * 128) + kb + b_cb);
                    ldsm_x4(rf[g2][0], rf[g2][1], rf[g2][2], rf[g2][3], kR + offB);
                    ldsm_x4(imf[g2][0], imf[g2][1], imf[g2][2], imf[g2][3], kI + offB);
                }
#pragma unroll
                for (int g2 = 0; g2 < 2; g2++) {
                    const int s2 = 2 * (gp * 2 + g2);
                    mma_fp16(sacc[s2],     aqr, rf[g2][0], rf[g2][1]);
                    mma_fp16(sacc[s2 + 1], aqr, rf[g2][2], rf[g2][3]);
                }
#pragma unroll
                for (int g2 = 0; g2 < 2; g2++) {
                    const int s2 = 2 * (gp * 2 + g2);
                    mma_fp16(sacc[s2],     aqi, imf[g2][0], imf[g2][1]);
                    mma_fp16(sacc[s2 + 1], aqi, imf[g2][2], imf[g2][3]);
                }
            }
        }

        float pm0 = -INFINITY, pm1 = -INFINITY;
#pragma unroll
        for (int f = 0; f < 8; f++) {
            const int sb2 = s0 + f * 8 + (lane & 3) * 2;
            const float2 gs0 = g_gate[h * SEQ + sb2];
            const float2 gs1 = g_gate[h * SEQ + sb2 + 1];
            float v00 = sacc[f][0] * SCALE_F * (gs0.x * gt0.x + gs0.y * gt0.y);
            float v01 = sacc[f][1] * SCALE_F * (gs1.x * gt0.x + gs1.y * gt0.y);
            float v10 = sacc[f][2] * SCALE_F * (gs0.x * gt1.x + gs0.y * gt1.y);
            float v11 = sacc[f][3] * SCALE_F * (gs1.x * gt1.x + gs1.y * gt1.y);
            if (sb2 > t0g)     v00 = -INFINITY;
            if (sb2 + 1 > t0g) v01 = -INFINITY;
            if (sb2 > t1g)     v10 = -INFINITY;
            if (sb2 + 1 > t1g) v11 = -INFINITY;
            sacc[f][0] = v00; sacc[f][1] = v01; sacc[f][2] = v10; sacc[f][3] = v11;
            pm0 = fmaxf(pm0, fmaxf(v00, v01));
            pm1 = fmaxf(pm1, fmaxf(v10, v11));
        }
        pm0 = fmaxf(pm0, __shfl_xor_sync(0xffffffffu, pm0, 1));
        pm0 = fmaxf(pm0, __shfl_xor_sync(0xffffffffu, pm0, 2));
        pm1 = fmaxf(pm1, __shfl_xor_sync(0xffffffffu, pm1, 1));
        pm1 = fmaxf(pm1, __shfl_xor_sync(0xffffffffu, pm1, 2));

        const float mn0 = fmaxf(m0, pm0), mn1 = fmaxf(m1, pm1);
        const float cr0 = __expf(m0 - mn0), cr1 = __expf(m1 - mn1);
        float rs0 = 0.f, rs1 = 0.f;
#pragma unroll
        for (int f = 0; f < 8; f++) {
            sacc[f][0] = __expf(sacc[f][0] - mn0);
            sacc[f][1] = __expf(sacc[f][1] - mn0);
            sacc[f][2] = __expf(sacc[f][2] - mn1);
            sacc[f][3] = __expf(sacc[f][3] - mn1);
            rs0 += sacc[f][0] + sacc[f][1];
            rs1 += sacc[f][2] + sacc[f][3];
        }
        rs0 += __shfl_xor_sync(0xffffffffu, rs0, 1);
        rs0 += __shfl_xor_sync(0xffffffffu, rs0, 2);
        rs1 += __shfl_xor_sync(0xffffffffu, rs1, 1);
        rs1 += __shfl_xor_sync(0xffffffffu, rs1, 2);
        l0 = l0 * cr0 + rs0; m0 = mn0;
        l1 = l1 * cr1 + rs1; m1 = mn1;
#pragma unroll
        for (int f = 0; f < 8; f++) {
            oacc[f][0] *= cr0; oacc[f][1] *= cr0;
            oacc[f][2] *= cr1; oacc[f][3] *= cr1;
        }

#pragma unroll
        for (int j = 0; j < 4; j++) {
            uint32_t ph[4] = {
                pack_half(sacc[2 * j][0],     sacc[2 * j][1]),
                pack_half(sacc[2 * j][2],     sacc[2 * j][3]),
                pack_half(sacc[2 * j + 1][0], sacc[2 * j + 1][1]),
                pack_half(sacc[2 * j + 1][2], sacc[2 * j + 1][3])};
#pragma unroll
            for (int dgp = 0; dgp < 2; dgp++) {
                uint32_t vf[2][4];
#pragma unroll
                for (int d2 = 0; d2 < 2; d2++) {
                    const int dg = dgp * 2 + d2;
                    const uint32_t offV = SWZ128((uint32_t)((16 * j + a_row) * 128) +
                                                 (uint32_t)(dg * 32) + a_cb);
                    ldsm_x4_t(vf[d2][0], vf[d2][1], vf[d2][2], vf[d2][3], vT + offV);
                }
#pragma unroll
                for (int d2 = 0; d2 < 2; d2++) {
                    const int o2 = 2 * (dgp * 2 + d2);
                    mma_fp16(oacc[o2],     ph, vf[d2][0], vf[d2][1]);
                    mma_fp16(oacc[o2 + 1], ph, vf[d2][2], vf[d2][3]);
                }
            }
        }
        __syncthreads();
        if (i + AKV_STAGES < nS && tid == 0) issue_kv(i + AKV_STAGES, stg);
    }

    // epilogue: normalize, write single fp16 in GEMM-A tiled layout
    const float iv0 = 1.0f / l0, iv1 = 1.0f / l1;
#pragma unroll
    for (int f = 0; f < 8; f++) {
        const int d = f * 8 + (lane & 3) * 2;
        size_t off0 = gemmA_off(b * SEQ + t0g, h * 64 + d);
        size_t off1 = gemmA_off(b * SEQ + t1g, h * 64 + d);
        *(uint32_t*)((char*)g_a + off0) = pack_half(oacc[f][0] * iv0, oacc[f][1] * iv0);
        *(uint32_t*)((char*)g_a + off1) = pack_half(oacc[f][2] * iv1, oacc[f][3] * iv1);
    }
}

// ---------------- launch ---------------------------------------------------
extern "C" void kernel_launch(void* const* d_in, const int* in_sizes, int n_in,
                              void* d_out, int out_size) {
    const float* x     = (const float*)d_in[0];
    const float* Wq    = (const float*)d_in[1];
    const float* Wk    = (const float*)d_in[2];
    const float* Wv    = (const float*)d_in[3];
    const float* Wo    = (const float*)d_in[4];
    const float* theta = (const float*)d_in[5];
    float* out = (float*)d_out;

    __half *qraw, *kraw;
    __half *xg, *ag, *vv, *wq, *wk, *wv, *wo;
    cudaGetSymbolAddress((void**)&qraw, g_qraw);
    cudaGetSymbolAddress((void**)&kraw, g_kraw);
    cudaGetSymbolAddress((void**)&xg,  g_x);
    cudaGetSymbolAddress((void**)&ag,  g_a);
    cudaGetSymbolAddress((void**)&vv,  g_vv);
    cudaGetSymbolAddress((void**)&wq,  g_wq);
    cudaGetSymbolAddress((void**)&wk,  g_wk);
    cudaGetSymbolAddress((void**)&wv,  g_wv);
    cudaGetSymbolAddress((void**)&wo,  g_wo);

    cudaFuncSetAttribute(gemm_qkv,
                         cudaFuncAttributeMaxDynamicSharedMemorySize, GEMM_SMEM);
    cudaFuncSetAttribute(gemm_out,
                         cudaFuncAttributeMaxDynamicSharedMemorySize, GEMM_SMEM);
    cudaFuncSetAttribute(attn_mma,
                         cudaFuncAttributeMaxDynamicSharedMemorySize, ATT_SMEM);

    prep_all<<<14464, dim3(32, 8)>>>(x, Wq, Wk, Wv, Wo, theta, xg, wq, wk, wv, wo);

    gemm_qkv<<<dim3(20, MROWS / 128), 256, GEMM_SMEM>>>(
        xg, wq, wk, wv, qraw, kraw, vv);

    transform_qk_fp16<<<MROWS * CDIM / 2 / 256, 256>>>();

    attn_mma<<<dim3(SEQ / AQT, HEADS, BATCH), 256, ATT_SMEM>>>();

    gemm_out<<<dim3(CDIM / 256, MROWS / 128), 256, GEMM_SMEM>>>(ag, wo, out, CDIM);
}

// round 17
// speedup vs baseline: 2.1566x; 1.0130x over previous
#include <cuda_runtime.h>
#include <cuda_bf16.h>
#include <cuda_fp16.h>
#include <cstdint>
#include <math.h>

// Problem constants
#define BATCH   2
#define SEQ     2048
#define CDIM    1024
#define HEADS   16
#define HDIM    64
#define GAMMA_F 8.0f
#define SCALE_F 0.125f
#define LOG2E_F 1.4426950408889634f
#define MROWS   (BATCH*SEQ)          // 4096
#define KDIM    1024

// ---------------- scratch (device globals; no allocation allowed) ----------
__device__ __half g_qraw[MROWS * 2 * CDIM];
__device__ __half g_kraw[MROWS * 2 * CDIM];

// fp16 GEMM operands (pre-swizzled tile-blocked layouts) -- ALL single fp16
__device__ __half g_x  [MROWS * CDIM];
__device__ __half g_a  [MROWS * CDIM];
__device__ __half g_wq [2 * CDIM * CDIM];
__device__ __half g_wk [2 * CDIM * CDIM];
__device__ __half g_wv [CDIM * CDIM];
__device__ __half g_wo [CDIM * CDIM];

// attention operands: ALL single fp16
__device__ __half g_qr [MROWS * CDIM];
__device__ __half g_qi [MROWS * CDIM];
__device__ __half g_kr [MROWS * CDIM];
__device__ __half g_ki [MROWS * CDIM];
__device__ __half g_vv [MROWS * CDIM];
__device__ float2 g_gate[HEADS * SEQ];

// ---------------- helpers ---------------------------------------------------
__device__ __forceinline__ uint32_t smem_u32(const void* p) {
    uint32_t a;
    asm("{ .reg .u64 t; cvta.to.shared.u64 t, %1; cvt.u32.u64 %0, t; }"
        : "=r"(a) : "l"(p));
    return a;
}
#define SWZ128(o) ((o) ^ (((o) >> 3) & 0x70))

__device__ __forceinline__ size_t gemmA_off(int row, int col) {
    return ((size_t)((row >> 7) * 16 + (col >> 6)) << 14) +
           SWZ128((uint32_t)((row & 127) * 128 + (col & 63) * 2));
}
__device__ __forceinline__ size_t att_off(int b, int h, int t, int d) {
    return ((size_t)((b * HEADS + h) * 32 + (t >> 6)) << 13) +
           SWZ128((uint32_t)((t & 63) * 128 + d * 2));
}

#define MBARRIER_INIT(mbar, count) \
    asm volatile("mbarrier.init.shared.b64 [%0], %1;" :: "r"((uint32_t)(mbar)), "r"((uint32_t)(count)) : "memory")
#define MBAR_EXPECT(mbar, bytes) \
    asm volatile("mbarrier.arrive.expect_tx.shared.b64 _, [%0], %1;" :: "r"((uint32_t)(mbar)), "r"((uint32_t)(bytes)) : "memory")

#define MBARRIER_WAIT_PARITY(mbar, parity) do { \
    uint32_t _m = (uint32_t)(mbar); uint32_t _p = (uint32_t)(parity); uint32_t _d; \
    asm volatile("{\n\t.reg .pred p;\n\t" \
        "mbarrier.try_wait.parity.acquire.cta.shared::cta.b64 p, [%1], %2;\n\t" \
        "selp.b32 %0, 1, 0, p;\n\t}" : "=r"(_d) : "r"(_m), "r"(_p) : "memory"); \
    if (!_d) { \
        asm volatile("{\n\t.reg .pred P1;\n\t" \
            "WL_%=:\n\t" \
            "mbarrier.try_wait.parity.acquire.cta.shared::cta.b64 P1, [%0], %1, 0x989680;\n\t" \
            "@P1 bra.uni WD_%=;\n\tbra.uni WL_%=;\n\tWD_%=:\n\t}" \
            :: "r"(_m), "r"(_p) : "memory"); \
    } } while (0)

__device__ __forceinline__ void bulk_g2s(uint32_t dst, const void* src,
                                         uint32_t bytes, uint32_t mbar) {
    asm volatile(
        "cp.async.bulk.shared::cluster.global.mbarrier::complete_tx::bytes [%0], [%1], %2, [%3];"
        :: "r"(dst), "l"(src), "r"(bytes), "r"(mbar) : "memory");
}

__device__ __forceinline__ void ldsm_x4(uint32_t& r0, uint32_t& r1,
                                        uint32_t& r2, uint32_t& r3, uint32_t addr) {
    asm volatile("ldmatrix.sync.aligned.m8n8.x4.shared.b16 {%0,%1,%2,%3}, [%4];"
                 : "=r"(r0), "=r"(r1), "=r"(r2), "=r"(r3) : "r"(addr));
}
__device__ __forceinline__ void ldsm_x4_t(uint32_t& r0, uint32_t& r1,
                                          uint32_t& r2, uint32_t& r3, uint32_t addr) {
    asm volatile("ldmatrix.sync.aligned.m8n8.x4.trans.shared.b16 {%0,%1,%2,%3}, [%4];"
                 : "=r"(r0), "=r"(r1), "=r"(r2), "=r"(r3) : "r"(addr));
}

__device__ __forceinline__ void mma_fp16(float* c, const uint32_t* a,
                                         uint32_t b0, uint32_t b1) {
    asm volatile(
        "mma.sync.aligned.m16n8k16.row.col.f32.f16.f16.f32 "
        "{%0,%1,%2,%3}, {%4,%5,%6,%7}, {%8,%9}, {%0,%1,%2,%3};"
        : "+f"(c[0]), "+f"(c[1]), "+f"(c[2]), "+f"(c[3])
        : "r"(a[0]), "r"(a[1]), "r"(a[2]), "r"(a[3]), "r"(b0), "r"(b1));
}

__device__ __forceinline__ uint32_t pack_half(float a, float b) {
    __half2 t = __floats2half2_rn(a, b);
    return *reinterpret_cast<uint32_t*>(&t);
}

// ---------------- single-fp16 GEMM (unchanged, validated R15/R16) ----------
#define BK       128
#define NCH      (KDIM / BK)             // 8
#define A_CHK    32768
#define STG_B    (3 * A_CHK)             // 98304
#define GSTAGES  2
#define GEMM_SMEM (1024 + GSTAGES * STG_B)  // 197632

__device__ __forceinline__ void gemm_body(
    const char* cA, const char* cB, int mb, int nb, float acc[4][8][4]) {
    extern __shared__ char smem[];
    const uint32_t sb = smem_u32(smem);
    const int tid = threadIdx.x, wid = tid >> 5, lane = tid & 31;
    const int wm = (wid & 1) * 64;
    const int wn = (wid >> 1) * 64;

    const size_t mbB  = ((size_t)mb * 16) << 14;
    const size_t nbB0 = ((size_t)(nb * 2) * 16) << 14;
    const size_t nbB1 = ((size_t)(nb * 2 + 1) * 16) << 14;

    if (tid == 0) { MBARRIER_INIT(sb, 1); MBARRIER_INIT(sb + 8, 1); }
    __syncthreads();

    auto issue = [&](int chunk, int buf) {
        const uint32_t st = sb + 1024 + buf * STG_B;
        const uint32_t bar = sb + buf * 8;
        const size_t kB = ((size_t)chunk) << 15;
        MBAR_EXPECT(bar, STG_B);
        bulk_g2s(st,             cA + mbB + kB,  A_CHK, bar);
        bulk_g2s(st + A_CHK,     cB + nbB0 + kB, A_CHK, bar);
        bulk_g2s(st + 2 * A_CHK, cB + nbB1 + kB, A_CHK, bar);
    };

    if (tid == 0) { issue(0, 0); issue(1, 1); }

#pragma unroll
    for (int i = 0; i < 4; i++)
#pragma unroll
        for (int j = 0; j < 8; j++)
#pragma unroll
            for (int e = 0; e < 4; e++) acc[i][j][e] = 0.f;

    const int a_row = (lane & 15);
    const uint32_t a_cb = (uint32_t)((lane >> 4) * 16);
    const int b_row = ((lane >> 4) & 1) * 8 + (lane & 7);
    const uint32_t b_cb = (uint32_t)(((lane >> 3) & 1) * 16);
    const int wn_loc = wn & 127;
    const uint32_t bHalfOff = (wn >= 128) ? A_CHK : 0;

    for (int i = 0; i < NCH; i++) {
        const int stg = i & 1;
        MBARRIER_WAIT_PARITY(sb + stg * 8, (i >> 1) & 1);

        const uint32_t st = sb + 1024 + stg * STG_B;

#pragma unroll
        for (int ks = 0; ks < 8; ks++) {
            const uint32_t sub = (uint32_t)((ks >> 2) * 16384);
            const uint32_t kb = (uint32_t)((ks & 3) * 32);
            const uint32_t aA = st + sub;
            const uint32_t bB = st + A_CHK + bHalfOff + sub;
            uint32_t af[4][4];
#pragma unroll
            for (int mi = 0; mi < 4; mi++) {
                uint32_t off = SWZ128((uint32_t)((wm + mi * 16 + a_row) * 128) + kb + a_cb);
                ldsm_x4(af[mi][0], af[mi][1], af[mi][2], af[mi][3], aA + off);
            }
#pragma unroll
            for (int hb = 0; hb < 2; hb++) {
                uint32_t bf[2][4];
#pragma unroll
                for (int g2 = 0; g2 < 2; g2++) {
                    const int ng = hb * 2 + g2;
                    uint32_t off = SWZ128((uint32_t)((wn_loc + ng * 16 + b_row) * 128) + kb + b_cb);
                    ldsm_x4(bf[g2][0], bf[g2][1], bf[g2][2], bf[g2][3], bB + off);
                }
#pragma unroll
                for (int g2 = 0; g2 < 2; g2++)
#pragma unroll
                    for (int mi = 0; mi < 4; mi++) {
                        const int nj = 2 * (hb * 2 + g2);
                        mma_fp16(acc[mi][nj],     af[mi], bf[g2][0], bf[g2][1]);
                        mma_fp16(acc[mi][nj + 1], af[mi], bf[g2][2], bf[g2][3]);
                    }
            }
        }
        __syncthreads();
        if (i + GSTAGES < NCH && tid == 0) issue(i + GSTAGES, stg);
    }
}

__device__ __forceinline__ void gemm_store_half(float acc[4][8][4], __half* Cm,
                                                int N, int m0, int n0) {
    const int tid = threadIdx.x, wid = tid >> 5, lane = tid & 31;
    const int wm = (wid & 1) * 64, wn = (wid >> 1) * 64;
    const int cr = lane >> 2;
    const int cc = (lane & 3) * 2;
#pragma unroll
    for (int mi = 0; mi < 4; mi++) {
#pragma unroll
        for (int nj = 0; nj < 8; nj++) {
            const int r = m0 + wm + mi * 16 + cr;
            const int c = n0 + wn + nj * 8 + cc;
            *(uint32_t*)&Cm[(size_t)r * N + c] = pack_half(acc[mi][nj][0], acc[mi][nj][1]);
            *(uint32_t*)&Cm[(size_t)(r + 8) * N + c] = pack_half(acc[mi][nj][2], acc[mi][nj][3]);
        }
    }
}

__device__ __forceinline__ void gemm_store_att(float acc[4][8][4], __half* Cm,
                                               int m0, int n0) {
    const int tid = threadIdx.x, wid = tid >> 5, lane = tid & 31;
    const int wm = (wid & 1) * 64, wn = (wid >> 1) * 64;
    const int cr = lane >> 2;
    const int cc = (lane & 3) * 2;
#pragma unroll
    for (int mi = 0; mi < 4; mi++) {
#pragma unroll
        for (int nj = 0; nj < 8; nj++) {
            const int c = n0 + wn + nj * 8 + cc;
            const int h = c >> 6, d = c & 63;
#pragma unroll
            for (int rr = 0; rr < 2; rr++) {
                const int r = m0 + wm + mi * 16 + cr + rr * 8;
                const int b = r >> 11, t = r & (SEQ - 1);
                *(uint32_t*)((char*)Cm + att_off(b, h, t, d)) =
                    pack_half(acc[mi][nj][2 * rr], acc[mi][nj][2 * rr + 1]);
            }
        }
    }
}

__device__ __forceinline__ void gemm_store_f32(float acc[4][8][4], float* Cm,
                                               int N, int m0, int n0) {
    const int tid = threadIdx.x, wid = tid >> 5, lane = tid & 31;
    const int wm = (wid & 1) * 64, wn = (wid >> 1) * 64;
    const int cr = lane >> 2;
    const int cc = (lane & 3) * 2;
#pragma unroll
    for (int mi = 0; mi < 4; mi++) {
#pragma unroll
        for (int nj = 0; nj < 8; nj++) {
            const int r = m0 + wm + mi * 16 + cr;
            const int c = n0 + wn + nj * 8 + cc;
            *(float2*)&Cm[(size_t)r * N + c] = make_float2(acc[mi][nj][0], acc[mi][nj][1]);
            *(float2*)&Cm[(size_t)(r + 8) * N + c] = make_float2(acc[mi][nj][2], acc[mi][nj][3]);
        }
    }
}

// Combined Q/K/V projection GEMM: grid.x = 20 (8 Q | 8 K | 4 V), grid.y = 32
__global__ __launch_bounds__(256, 1)
void gemm_qkv(const __half* __restrict__ x,
              const __half* __restrict__ wq, const __half* __restrict__ wk,
              const __half* __restrict__ wv,
              __half* __restrict__ qraw, __half* __restrict__ kraw,
              __half* __restrict__ vatt) {
    const int nx = blockIdx.x;
    float acc[4][8][4];
    if (nx < 8) {
        gemm_body((const char*)x, (const char*)wq, blockIdx.y, nx, acc);
        gemm_store_half(acc, qraw, 2 * CDIM, blockIdx.y * 128, nx * 256);
    } else if (nx < 16) {
        gemm_body((const char*)x, (const char*)wk, blockIdx.y, nx - 8, acc);
        gemm_store_half(acc, kraw, 2 * CDIM, blockIdx.y * 128, (nx - 8) * 256);
    } else {
        gemm_body((const char*)x, (const char*)wv, blockIdx.y, nx - 16, acc);
        gemm_store_att(acc, vatt, blockIdx.y * 128, (nx - 16) * 256);
    }
}

__global__ __launch_bounds__(256, 1)
void gemm_out(const __half* __restrict__ A, const __half* __restrict__ B,
              float* __restrict__ Cm, int N) {
    float acc[4][8][4];
    gemm_body((const char*)A, (const char*)B, blockIdx.y, blockIdx.x, acc);
    gemm_store_f32(acc, Cm, N, blockIdx.y * 128, blockIdx.x * 256);
}

// ---------------- merged prep: weight transposes + x convert + gate ---------
__global__ __launch_bounds__(256)
void prep_all(const float* __restrict__ x,
              const float* __restrict__ Wq, const float* __restrict__ Wk,
              const float* __restrict__ Wv, const float* __restrict__ Wo,
              const float* __restrict__ theta,
              __half* __restrict__ Dx,
              __half* __restrict__ Dq, __half* __restrict__ Dk,
              __half* __restrict__ Dv, __half* __restrict__ Do_) {
    int bid = blockIdx.x;
    const int tid1 = threadIdx.y * 32 + threadIdx.x;

    if (bid < 6144) {
        __shared__ float t[32][33];
        const float* W;
        __half* D;
        int N, nb, kb;
        if (bid < 2048)      { W = Wq; D = Dq; N = 2 * CDIM; nb = bid & 63; kb = bid >> 6; }
        else if (bid < 4096) { bid -= 2048; W = Wk; D = Dk; N = 2 * CDIM; nb = bid & 63; kb = bid >> 6; }
        else if (bid < 5120) { bid -= 4096; W = Wv; D = Dv; N = CDIM; nb = bid & 31; kb = bid >> 5; }
        else                 { bid -= 5120; W = Wo; D = Do_; N = CDIM; nb = bid & 31; kb = bid >> 5; }

        const int tx = threadIdx.x, ty = threadIdx.y;
        const int n0 = nb * 32, k0 = kb * 32;
#pragma unroll
        for (int i = 0; i < 32; i += 8)
            t[ty + i][tx] = W[(size_t)(k0 + ty + i) * N + n0 + tx];
        __syncthreads();
#pragma unroll
        for (int i = 0; i < 32; i += 8) {
            float v = t[tx][ty + i];
            size_t off = gemmA_off(n0 + ty + i, k0 + tx);
            *(__half*)((char*)D + off) = __float2half(v);
        }
    } else if (bid < 14336) {
        int i2 = (bid - 6144) * 256 + tid1;
        int row = i2 >> 9, col = (i2 & 511) * 2;
        float2 v = *(const float2*)&x[(size_t)row * CDIM + col];
        size_t off = gemmA_off(row, col);
        *(uint32_t*)((char*)Dx + off) = pack_half(v.x, v.y);
    } else {
        int i = (bid - 14336) * 256 + tid1;
        int h = i >> 11, s = i & (SEQ - 1);
        float th = theta[h] * (1.0f / GAMMA_F);
        float sn, cs;
        sincosf(th * (float)s, &sn, &cs);
        g_gate[i] = make_float2(cs, sn);
    }
}

// ---------------- amp/phase transform (fp16 in) -> single fp16 --------------
__device__ __forceinline__ float softplus_f(float a) {
    return (a > 20.f) ? a : log1pf(expf(a));
}

__global__ __launch_bounds__(256)
void transform_qk_fp16() {
    int i2 = blockIdx.x * 256 + threadIdx.x;
    int c2 = i2 * 2;
    int bt = c2 >> 10;
    int c  = c2 & 1023;
    int b = bt >> 11, t = bt & (SEQ - 1);
    int h = c >> 6, d = c & 63;
    size_t rbase = (size_t)bt * (2 * CDIM);
    size_t off = att_off(b, h, t, d);

    __half2 qa = *(const __half2*)&g_qraw[rbase + c];
    __half2 qp = *(const __half2*)&g_qraw[rbase + CDIM + c];
    __half2 ka = *(const __half2*)&g_kraw[rbase + c];
    __half2 kp = *(const __half2*)&g_kraw[rbase + CDIM + c];

    float qa0 = __half2float(qa.x), qa1 = __half2float(qa.y);
    float qp0 = __half2float(qp.x), qp1 = __half2float(qp.y);
    float ka0 = __half2float(ka.x), ka1 = __half2float(ka.y);
    float kp0 = __half2float(kp.x), kp1 = __half2float(kp.y);

    float qs0 = softplus_f(qa0), qs1 = softplus_f(qa1);
    float ks0 = softplus_f(ka0), ks1 = softplus_f(ka1);
    float s0, c0, s1, c1, s2, c2f, s3, c3;
    sincosf(qp0, &s0, &c0); sincosf(qp1, &s1, &c1);
    sincosf(kp0, &s2, &c2f); sincosf(kp1, &s3, &c3);

    *(uint32_t*)((char*)g_qr + off) = pack_half(qs0 * c0, qs1 * c1);
    *(uint32_t*)((char*)g_qi + off) = pack_half(qs0 * s0, qs1 * s1);
    *(uint32_t*)((char*)g_kr + off) = pack_half(ks0 * c2f, ks1 * c3);
    *(uint32_t*)((char*)g_ki + off) = pack_half(ks0 * s2, ks1 * s3);
}

// ---------------- fully fp16 flash attention with moiré gate ----------------
// 2 CTAs/SM (128 regs, 83KB smem), 2-stage KV pipe, log2-domain softmax.
#define AQT 128
#define AST 64
#define AQ_TILE 16384
#define AKV_TILE 8192
#define AKV_BUF (3 * AKV_TILE)              // 24576
#define AKV_STAGES 2
#define ATT_SMEM (1024 + 2 * AQ_TILE + AKV_STAGES * AKV_BUF)  // 82944

__global__ __launch_bounds__(256, 2)
void attn_mma() {
    extern __shared__ char smem[];
    const uint32_t sb = smem_u32(smem);
    const uint32_t sQ  = sb + 1024;
    const uint32_t sKV = sQ + 2 * AQ_TILE;

    const int tid = threadIdx.x, w = tid >> 5, lane = tid & 31;
    const int q0 = (int)(gridDim.x - 1 - blockIdx.x) * AQT;
    const int h = blockIdx.y, b = blockIdx.z;
    const int nS = q0 / AST + 2;

    const size_t bhB = ((size_t)((b * HEADS + h) * 32)) << 13;

    if (tid == 0) {
        MBARRIER_INIT(sb, 1);
#pragma unroll
        for (int s = 0; s < AKV_STAGES; s++) MBARRIER_INIT(sb + 8 + s * 8, 1);
    }
    __syncthreads();

    auto issue_kv = [&](int chunk, int buf) {
        const uint32_t st = sKV + buf * AKV_BUF;
        const uint32_t bar = sb + 8 + buf * 8;
        const size_t src = bhB + (((size_t)chunk) << 13);
        MBAR_EXPECT(bar, AKV_BUF);
        bulk_g2s(st,                (const char*)g_kr + src, AKV_TILE, bar);
        bulk_g2s(st + AKV_TILE,     (const char*)g_ki + src, AKV_TILE, bar);
        bulk_g2s(st + 2 * AKV_TILE, (const char*)g_vv + src, AKV_TILE, bar);
    };

    if (tid == 0) {
        const size_t qsrc = bhB + (((size_t)(q0 >> 6)) << 13);
        MBAR_EXPECT(sb, 2 * AQ_TILE);
        bulk_g2s(sQ,           (const char*)g_qr + qsrc, AQ_TILE, sb);
        bulk_g2s(sQ + AQ_TILE, (const char*)g_qi + qsrc, AQ_TILE, sb);
#pragma unroll
        for (int c = 0; c < AKV_STAGES; c++)
            if (c < nS) issue_kv(c, c);
    }

    const int a_row = lane & 15;
    const uint32_t a_cb = (uint32_t)((lane >> 4) * 16);
    const int b_row = ((lane >> 4) & 1) * 8 + (lane & 7);
    const uint32_t b_cb = (uint32_t)(((lane >> 3) & 1) * 16);

    const int t0g = q0 + w * 16 + (lane >> 2);
    const int t1g = t0g + 8;
    const float2 gt0 = g_gate[h * SEQ + t0g];
    const float2 gt1 = g_gate[h * SEQ + t1g];

    // log2-domain running max/sum
    float m0 = -INFINITY, m1 = -INFINITY, l0 = 0.f, l1 = 0.f;
    float oacc[8][4];
#pragma unroll
    for (int f = 0; f < 8; f++)
#pragma unroll
        for (int e = 0; e < 4; e++) oacc[f][e] = 0.f;

    const float SC2 = SCALE_F * LOG2E_F;

    MBARRIER_WAIT_PARITY(sb, 0);

    for (int i = 0; i < nS; i++) {
        const int stg = i % AKV_STAGES;
        MBARRIER_WAIT_PARITY(sb + 8 + stg * 8, (i / AKV_STAGES) & 1);

        const int s0 = i * AST;
        const uint32_t kb0 = sKV + stg * AKV_BUF;
        const uint32_t kR = kb0, kI = kb0 + AKV_TILE, vT = kb0 + 2 * AKV_TILE;

        float sacc[8][4];
#pragma unroll
        for (int f = 0; f < 8; f++)
#pragma unroll
            for (int e = 0; e < 4; e++) sacc[f][e] = 0.f;

#pragma unroll
        for (int jd = 0; jd < 4; jd++) {
            const uint32_t kb = (uint32_t)(jd * 32);
            const uint32_t offA = SWZ128((uint32_t)((w * 16 + a_row) * 128) + kb + a_cb);
            uint32_t aqr[4], aqi[4];
            ldsm_x4(aqr[0], aqr[1], aqr[2], aqr[3], sQ + offA);
            ldsm_x4(aqi[0], aqi[1], aqi[2], aqi[3], sQ + AQ_TILE + offA);
#pragma unroll
            for (int gp = 0; gp < 2; gp++) {
                uint32_t rf[2][4], imf[2][4];
#pragma unroll
                for (int g2 = 0; g2 < 2; g2++) {
                    const int g = gp * 2 + g2;
                    const uint32_t offB = SWZ128((uint32_t)((g * 16 + b_row) * 128) + kb + b_cb);
                    ldsm_x4(rf[g2][0], rf[g2][1], rf[g2][2], rf[g2][3], kR + offB);
                    ldsm_x4(imf[g2][0], imf[g2][1], imf[g2][2], imf[g2][3], kI + offB);
                }
#pragma unroll
                for (int g2 = 0; g2 < 2; g2++) {
                    const int s2 = 2 * (gp * 2 + g2);
                    mma_fp16(sacc[s2],     aqr, rf[g2][0], rf[g2][1]);
                    mma_fp16(sacc[s2 + 1], aqr, rf[g2][2], rf[g2][3]);
                }
#pragma unroll
                for (int g2 = 0; g2 < 2; g2++) {
                    const int s2 = 2 * (gp * 2 + g2);
                    mma_fp16(sacc[s2],     aqi, imf[g2][0], imf[g2][1]);
                    mma_fp16(sacc[s2 + 1], aqi, imf[g2][2], imf[g2][3]);
                }
            }
        }

        float pm0 = -INFINITY, pm1 = -INFINITY;
#pragma unroll
        for (int f = 0; f < 8; f++) {
            const int sb2 = s0 + f * 8 + (lane & 3) * 2;
            const float2 gs0 = g_gate[h * SEQ + sb2];
            const float2 gs1 = g_gate[h * SEQ + sb2 + 1];
            float v00 = sacc[f][0] * SC2 * (gs0.x * gt0.x + gs0.y * gt0.y);
            float v01 = sacc[f][1] * SC2 * (gs1.x * gt0.x + gs1.y * gt0.y);
            float v10 = sacc[f][2] * SC2 * (gs0.x * gt1.x + gs0.y * gt1.y);
            float v11 = sacc[f][3] * SC2 * (gs1.x * gt1.x + gs1.y * gt1.y);
            if (sb2 > t0g)     v00 = -INFINITY;
            if (sb2 + 1 > t0g) v01 = -INFINITY;
            if (sb2 > t1g)     v10 = -INFINITY;
            if (sb2 + 1 > t1g) v11 = -INFINITY;
            sacc[f][0] = v00; sacc[f][1] = v01; sacc[f][2] = v10; sacc[f][3] = v11;
            pm0 = fmaxf(pm0, fmaxf(v00, v01));
            pm1 = fmaxf(pm1, fmaxf(v10, v11));
        }
        pm0 = fmaxf(pm0, __shfl_xor_sync(0xffffffffu, pm0, 1));
        pm0 = fmaxf(pm0, __shfl_xor_sync(0xffffffffu, pm0, 2));
        pm1 = fmaxf(pm1, __shfl_xor_sync(0xffffffffu, pm1, 1));
        pm1 = fmaxf(pm1, __shfl_xor_sync(0xffffffffu, pm1, 2));

        const float mn0 = fmaxf(m0, pm0), mn1 = fmaxf(m1, pm1);
        const float cr0 = exp2f(m0 - mn0), cr1 = exp2f(m1 - mn1);
        float rs0 = 0.f, rs1 = 0.f;
#pragma unroll
        for (int f = 0; f < 8; f++) {
            sacc[f][0] = exp2f(sacc[f][0] - mn0);
            sacc[f][1] = exp2f(sacc[f][1] - mn0);
            sacc[f][2] = exp2f(sacc[f][2] - mn1);
            sacc[f][3] = exp2f(sacc[f][3] - mn1);
            rs0 += sacc[f][0] + sacc[f][1];
            rs1 += sacc[f][2] + sacc[f][3];
        }
        rs0 += __shfl_xor_sync(0xffffffffu, rs0, 1);
        rs0 += __shfl_xor_sync(0xffffffffu, rs0, 2);
        rs1 += __shfl_xor_sync(0xffffffffu, rs1, 1);
        rs1 += __shfl_xor_sync(0xffffffffu, rs1, 2);
        l0 = l0 * cr0 + rs0; m0 = mn0;
        l1 = l1 * cr1 + rs1; m1 = mn1;
#pragma unroll
        for (int f = 0; f < 8; f++) {
            oacc[f][0] *= cr0; oacc[f][1] *= cr0;
            oacc[f][2] *= cr1; oacc[f][3] *= cr1;
        }

#pragma unroll
        for (int j = 0; j < 4; j++) {
            uint32_t ph[4] = {
                pack_half(sacc[2 * j][0],     sacc[2 * j][1]),
                pack_half(sacc[2 * j][2],     sacc[2 * j][3]),
                pack_half(sacc[2 * j + 1][0], sacc[2 * j + 1][1]),
                pack_half(sacc[2 * j + 1][2], sacc[2 * j + 1][3])};
#pragma unroll
            for (int dgp = 0; dgp < 2; dgp++) {
                uint32_t vf[2][4];
#pragma unroll
                for (int d2 = 0; d2 < 2; d2++) {
                    const int dg = dgp * 2 + d2;
                    const uint32_t offV = SWZ128((uint32_t)((16 * j + a_row) * 128) +
                                                 (uint32_t)(dg * 32) + a_cb);
                    ldsm_x4_t(vf[d2][0], vf[d2][1], vf[d2][2], vf[d2][3], vT + offV);
                }
#pragma unroll
                for (int d2 = 0; d2 < 2; d2++) {
                    const int o2 = 2 * (dgp * 2 + d2);
                    mma_fp16(oacc[o2],     ph, vf[d2][0], vf[d2][1]);
                    mma_fp16(oacc[o2 + 1], ph, vf[d2][2], vf[d2][3]);
                }
            }
        }
        __syncthreads();
        if (i + AKV_STAGES < nS && tid == 0) issue_kv(i + AKV_STAGES, stg);
    }

    // epilogue: normalize, write single fp16 in GEMM-A tiled layout
    const float iv0 = 1.0f / l0, iv1 = 1.0f / l1;
#pragma unroll
    for (int f = 0; f < 8; f++) {
        const int d = f * 8 + (lane & 3) * 2;
        size_t off0 = gemmA_off(b * SEQ + t0g, h * 64 + d);
        size_t off1 = gemmA_off(b * SEQ + t1g, h * 64 + d);
        *(uint32_t*)((char*)g_a + off0) = pack_half(oacc[f][0] * iv0, oacc[f][1] * iv0);
        *(uint32_t*)((char*)g_a + off1) = pack_half(oacc[f][2] * iv1, oacc[f][3] * iv1);
    }
}

// ---------------- launch ---------------------------------------------------
extern "C" void kernel_launch(void* const* d_in, const int* in_sizes, int n_in,
                              void* d_out, int out_size) {
    const float* x     = (const float*)d_in[0];
    const float* Wq    = (const float*)d_in[1];
    const float* Wk    = (const float*)d_in[2];
    const float* Wv    = (const float*)d_in[3];
    const float* Wo    = (const float*)d_in[4];
    const float* theta = (const float*)d_in[5];
    float* out = (float*)d_out;

    __half *qraw, *kraw;
    __half *xg, *ag, *vv, *wq, *wk, *wv, *wo;
    cudaGetSymbolAddress((void**)&qraw, g_qraw);
    cudaGetSymbolAddress((void**)&kraw, g_kraw);
    cudaGetSymbolAddress((void**)&xg,  g_x);
    cudaGetSymbolAddress((void**)&ag,  g_a);
    cudaGetSymbolAddress((void**)&vv,  g_vv);
    cudaGetSymbolAddress((void**)&wq,  g_wq);
    cudaGetSymbolAddress((void**)&wk,  g_wk);
    cudaGetSymbolAddress((void**)&wv,  g_wv);
    cudaGetSymbolAddress((void**)&wo,  g_wo);

    cudaFuncSetAttribute(gemm_qkv,
                         cudaFuncAttributeMaxDynamicSharedMemorySize, GEMM_SMEM);
    cudaFuncSetAttribute(gemm_out,
                         cudaFuncAttributeMaxDynamicSharedMemorySize, GEMM_SMEM);
    cudaFuncSetAttribute(attn_mma,
                         cudaFuncAttributeMaxDynamicSharedMemorySize, ATT_SMEM);

    prep_all<<<14464, dim3(32, 8)>>>(x, Wq, Wk, Wv, Wo, theta, xg, wq, wk, wv, wo);

    gemm_qkv<<<dim3(20, MROWS / 128), 256, GEMM_SMEM>>>(
        xg, wq, wk, wv, qraw, kraw, vv);

    transform_qk_fp16<<<MROWS * CDIM / 2 / 256, 256>>>();

    attn_mma<<<dim3(SEQ / AQT, HEADS, BATCH), 256, ATT_SMEM>>>();

    gemm_out<<<dim3(CDIM / 256, MROWS / 128), 256, GEMM_SMEM>>>(ag, wo, out, CDIM);
}